// round 1
// baseline (speedup 1.0000x reference)
#include <cuda_runtime.h>
#include <math.h>

#define S_LEN 2048
#define B_SZ  2
#define DM    1024
#define NH    16
#define DK    64
#define MROWS (B_SZ * S_LEN)   // 4096

// Scratch (no allocations allowed) — 4 x 16.8 MB
__device__ float g_Q[MROWS * DM];
__device__ float g_K[MROWS * DM];
__device__ float g_V[MROWS * DM];
__device__ float g_AO[MROWS * DM];

// ---------------------------------------------------------------------------
// C[M,N] = A[M,K] @ W[N,K]^T + bias[N]   (both operands K-contiguous)
// 128x128 tile, BK=8, 256 threads, 8x8 register tile.
// ---------------------------------------------------------------------------
__global__ __launch_bounds__(256) void gemm_tn_bias(
    const float* __restrict__ A, const float* __restrict__ W,
    const float* __restrict__ bias, float* __restrict__ C,
    int M, int N, int K)
{
    __shared__ float As[8][128];
    __shared__ float Ws[8][128];

    const int tid = threadIdx.x;
    const int bm  = blockIdx.y * 128;
    const int bn  = blockIdx.x * 128;
    const int tx  = tid & 15;        // 0..15 -> 8 output cols each
    const int ty  = tid >> 4;        // 0..15 -> 8 output rows each
    const int lr  = tid >> 1;        // 0..127 load row
    const int lk  = (tid & 1) * 4;   // 0 or 4

    float acc[8][8];
    #pragma unroll
    for (int i = 0; i < 8; i++)
        #pragma unroll
        for (int j = 0; j < 8; j++) acc[i][j] = 0.f;

    const float* Aptr = A + (size_t)(bm + lr) * K + lk;
    const float* Wptr = W + (size_t)(bn + lr) * K + lk;

    for (int k0 = 0; k0 < K; k0 += 8) {
        float4 a4 = *(const float4*)(Aptr + k0);
        float4 w4 = *(const float4*)(Wptr + k0);
        As[lk + 0][lr] = a4.x; As[lk + 1][lr] = a4.y;
        As[lk + 2][lr] = a4.z; As[lk + 3][lr] = a4.w;
        Ws[lk + 0][lr] = w4.x; Ws[lk + 1][lr] = w4.y;
        Ws[lk + 2][lr] = w4.z; Ws[lk + 3][lr] = w4.w;
        __syncthreads();

        #pragma unroll
        for (int kk = 0; kk < 8; kk++) {
            float ar[8], wr[8];
            *(float4*)&ar[0] = *(const float4*)&As[kk][ty * 8];
            *(float4*)&ar[4] = *(const float4*)&As[kk][ty * 8 + 4];
            *(float4*)&wr[0] = *(const float4*)&Ws[kk][tx * 8];
            *(float4*)&wr[4] = *(const float4*)&Ws[kk][tx * 8 + 4];
            #pragma unroll
            for (int i = 0; i < 8; i++)
                #pragma unroll
                for (int j = 0; j < 8; j++)
                    acc[i][j] += ar[i] * wr[j];
        }
        __syncthreads();
    }

    #pragma unroll
    for (int i = 0; i < 8; i++) {
        const int row = bm + ty * 8 + i;
        #pragma unroll
        for (int j = 0; j < 8; j += 4) {
            const int col = bn + tx * 8 + j;
            float4 o;
            o.x = acc[i][j + 0] + bias[col + 0];
            o.y = acc[i][j + 1] + bias[col + 1];
            o.z = acc[i][j + 2] + bias[col + 2];
            o.w = acc[i][j + 3] + bias[col + 3];
            *(float4*)&C[(size_t)row * N + col] = o;
        }
    }
}

// ---------------------------------------------------------------------------
// Flash attention, fp32. One CTA = 64 queries x one (b,h).
// 256 threads as 16x16; each thread owns a 4x4 tile of S / P and of O.
// smem: Qs[64][64], Ks[64][65], Vs[64][65], Ps[64][65]  (66304 B dynamic)
// ---------------------------------------------------------------------------
#define BMQ 64
#define BNK 64
#define ATT_SMEM_FLOATS (64 * 64 + 3 * 64 * 65)

__global__ __launch_bounds__(256) void flash_attn(
    const float* __restrict__ Q, const float* __restrict__ K,
    const float* __restrict__ V, const int* __restrict__ mask,
    float* __restrict__ O)
{
    extern __shared__ float sm[];
    float* Qs = sm;                 // [i][d]  stride 64
    float* Ks = Qs + 64 * 64;       // [j][d]  stride 65
    float* Vs = Ks + 64 * 65;       // [j][d]  stride 65
    float* Ps = Vs + 64 * 65;       // [j][i]  stride 65

    const int tid = threadIdx.x;
    const int tx  = tid & 15;
    const int ty  = tid >> 4;
    const int qb  = blockIdx.x;          // query block 0..31
    const int bh  = blockIdx.y;          // 0..31
    const int b   = bh >> 4;
    const int h   = bh & 15;
    const int q0  = qb * BMQ;
    const int rowbase = b * S_LEN;
    const int hoff = h * DK;

    const int i0 = ty * 4;   // local query rows
    const int cc = tx * 4;   // local score-col / out-d cols

    // ---- load Q tile: [64 rows][64 d], vectorized, natural layout ----
    #pragma unroll
    for (int t = 0; t < 4; t++) {
        int f4 = tid + t * 256;              // 0..1023
        int i  = f4 >> 4;
        int d4 = (f4 & 15) << 2;
        float4 v = *(const float4*)&Q[(size_t)(rowbase + q0 + i) * DM + hoff + d4];
        *(float4*)&Qs[i * 64 + d4] = v;
    }

    float m_i[4], l_i[4], o_acc[4][4];
    #pragma unroll
    for (int r = 0; r < 4; r++) {
        m_i[r] = -3.0e38f;
        l_i[r] = 0.f;
        #pragma unroll
        for (int c = 0; c < 4; c++) o_acc[r][c] = 0.f;
    }

    for (int kb = 0; kb < S_LEN / BNK; kb++) {
        const int k0g = kb * BNK;

        // ---- load K, V tiles (coalesced float4, scalar STS due to +65 pad) ----
        #pragma unroll
        for (int t = 0; t < 4; t++) {
            int f4 = tid + t * 256;
            int j  = f4 >> 4;
            int d4 = (f4 & 15) << 2;
            float4 kv = *(const float4*)&K[(size_t)(rowbase + k0g + j) * DM + hoff + d4];
            float4 vv = *(const float4*)&V[(size_t)(rowbase + k0g + j) * DM + hoff + d4];
            float* kd = &Ks[j * 65 + d4];
            kd[0] = kv.x; kd[1] = kv.y; kd[2] = kv.z; kd[3] = kv.w;
            float* vd = &Vs[j * 65 + d4];
            vd[0] = vv.x; vd[1] = vv.y; vd[2] = vv.z; vd[3] = vv.w;
        }
        __syncthreads();

        // ---- S = Q @ K^T tile (4x4 per thread) ----
        float s[4][4];
        #pragma unroll
        for (int r = 0; r < 4; r++)
            #pragma unroll
            for (int c = 0; c < 4; c++) s[r][c] = 0.f;

        #pragma unroll 8
        for (int d = 0; d < 64; d++) {
            float qv[4], kv[4];
            #pragma unroll
            for (int r = 0; r < 4; r++) qv[r] = Qs[(i0 + r) * 64 + d];
            #pragma unroll
            for (int c = 0; c < 4; c++) kv[c] = Ks[(cc + c) * 65 + d];
            #pragma unroll
            for (int r = 0; r < 4; r++)
                #pragma unroll
                for (int c = 0; c < 4; c++)
                    s[r][c] += qv[r] * kv[c];
        }

        // ---- scale + mask (reference order: scale, then where -> -1e9) ----
        #pragma unroll
        for (int r = 0; r < 4; r++) {
            const int qg = q0 + i0 + r;
            #pragma unroll
            for (int c = 0; c < 4; c++) {
                float sv = s[r][c] * 0.125f;   // 1/sqrt(64)
                int mv = mask[(size_t)qg * S_LEN + k0g + cc + c];
                s[r][c] = (mv == 0) ? -1e9f : sv;
            }
        }

        // ---- online softmax update (row groups = 16 lanes, same ty) ----
        #pragma unroll
        for (int r = 0; r < 4; r++) {
            float rm = fmaxf(fmaxf(s[r][0], s[r][1]), fmaxf(s[r][2], s[r][3]));
            rm = fmaxf(rm, __shfl_xor_sync(0xffffffffu, rm, 1));
            rm = fmaxf(rm, __shfl_xor_sync(0xffffffffu, rm, 2));
            rm = fmaxf(rm, __shfl_xor_sync(0xffffffffu, rm, 4));
            rm = fmaxf(rm, __shfl_xor_sync(0xffffffffu, rm, 8));
            float mn = fmaxf(m_i[r], rm);
            float alpha = __expf(m_i[r] - mn);
            float rs = 0.f;
            #pragma unroll
            for (int c = 0; c < 4; c++) {
                s[r][c] = __expf(s[r][c] - mn);
                rs += s[r][c];
            }
            rs += __shfl_xor_sync(0xffffffffu, rs, 1);
            rs += __shfl_xor_sync(0xffffffffu, rs, 2);
            rs += __shfl_xor_sync(0xffffffffu, rs, 4);
            rs += __shfl_xor_sync(0xffffffffu, rs, 8);
            l_i[r] = l_i[r] * alpha + rs;
            m_i[r] = mn;
            #pragma unroll
            for (int c = 0; c < 4; c++) o_acc[r][c] *= alpha;
        }

        // ---- store P transposed: Ps[j][i] ----
        #pragma unroll
        for (int c = 0; c < 4; c++)
            #pragma unroll
            for (int r = 0; r < 4; r++)
                Ps[(cc + c) * 65 + i0 + r] = s[r][c];
        __syncthreads();

        // ---- O += P @ V ----
        #pragma unroll 8
        for (int j = 0; j < 64; j++) {
            float pv[4], vv[4];
            #pragma unroll
            for (int r = 0; r < 4; r++) pv[r] = Ps[j * 65 + i0 + r];
            #pragma unroll
            for (int c = 0; c < 4; c++) vv[c] = Vs[j * 65 + cc + c];
            #pragma unroll
            for (int r = 0; r < 4; r++)
                #pragma unroll
                for (int c = 0; c < 4; c++)
                    o_acc[r][c] += pv[r] * vv[c];
        }
        __syncthreads();
    }

    // ---- epilogue: O / l, write [B,S,D] layout ----
    #pragma unroll
    for (int r = 0; r < 4; r++) {
        float inv = 1.f / l_i[r];
        float4 o;
        o.x = o_acc[r][0] * inv;
        o.y = o_acc[r][1] * inv;
        o.z = o_acc[r][2] * inv;
        o.w = o_acc[r][3] * inv;
        *(float4*)&O[(size_t)(rowbase + q0 + i0 + r) * DM + hoff + cc] = o;
    }
}

// ---------------------------------------------------------------------------
extern "C" void kernel_launch(void* const* d_in, const int* in_sizes, int n_in,
                              void* d_out, int out_size)
{
    const float* q    = (const float*)d_in[0];
    const float* k    = (const float*)d_in[1];
    const float* v    = (const float*)d_in[2];
    const int*   mask = (const int*)  d_in[3];
    const float* Wq   = (const float*)d_in[4];
    const float* bq   = (const float*)d_in[5];
    const float* Wk   = (const float*)d_in[6];
    const float* bk   = (const float*)d_in[7];
    const float* Wv   = (const float*)d_in[8];
    const float* bv   = (const float*)d_in[9];
    const float* Wo   = (const float*)d_in[10];
    const float* bo   = (const float*)d_in[11];
    float* out = (float*)d_out;

    float *gQ, *gK, *gV, *gAO;
    cudaGetSymbolAddress((void**)&gQ,  g_Q);
    cudaGetSymbolAddress((void**)&gK,  g_K);
    cudaGetSymbolAddress((void**)&gV,  g_V);
    cudaGetSymbolAddress((void**)&gAO, g_AO);

    const int smem_bytes = ATT_SMEM_FLOATS * sizeof(float);
    cudaFuncSetAttribute(flash_attn, cudaFuncAttributeMaxDynamicSharedMemorySize,
                         smem_bytes);

    dim3 gg(DM / 128, MROWS / 128);   // (8, 32)

    gemm_tn_bias<<<gg, 256>>>(q, Wq, bq, gQ, MROWS, DM, DM);
    gemm_tn_bias<<<gg, 256>>>(k, Wk, bk, gK, MROWS, DM, DM);
    gemm_tn_bias<<<gg, 256>>>(v, Wv, bv, gV, MROWS, DM, DM);

    dim3 ga(S_LEN / BMQ, B_SZ * NH);  // (32, 32)
    flash_attn<<<ga, 256, smem_bytes>>>(gQ, gK, gV, mask, gAO);

    gemm_tn_bias<<<gg, 256>>>(gAO, Wo, bo, out, MROWS, DM, DM);
}

// round 4
// speedup vs baseline: 1.4082x; 1.4082x over previous
#include <cuda_runtime.h>
#include <cuda_bf16.h>
#include <cstdint>
#include <math.h>

#define S_LEN 2048
#define B_SZ  2
#define DM    1024
#define NH    16
#define DK    64
#define MROWS (B_SZ * S_LEN)   // 4096

// ---------------------------------------------------------------------------
// Scratch (static device memory; no allocations allowed)
// ---------------------------------------------------------------------------
__device__ float g_Q[MROWS * DM];
__device__ float g_K[MROWS * DM];
__device__ float g_V[MROWS * DM];
__device__ float g_AO[MROWS * DM];

__device__ __nv_bfloat16 g_q_hi[MROWS * DM], g_q_lo[MROWS * DM];
__device__ __nv_bfloat16 g_k_hi[MROWS * DM], g_k_lo[MROWS * DM];
__device__ __nv_bfloat16 g_v_hi[MROWS * DM], g_v_lo[MROWS * DM];
__device__ __nv_bfloat16 g_ao_hi[MROWS * DM], g_ao_lo[MROWS * DM];
__device__ __nv_bfloat16 g_Wq_hi[DM * DM], g_Wq_lo[DM * DM];
__device__ __nv_bfloat16 g_Wk_hi[DM * DM], g_Wk_lo[DM * DM];
__device__ __nv_bfloat16 g_Wv_hi[DM * DM], g_Wv_lo[DM * DM];
__device__ __nv_bfloat16 g_Wo_hi[DM * DM], g_Wo_lo[DM * DM];

// ---------------------------------------------------------------------------
// HMMA helpers (base sm_100 target: mma.sync + ldmatrix, NO tcgen05)
// ---------------------------------------------------------------------------
__device__ __forceinline__ uint32_t smem_u32(const void* p) {
    uint32_t a;
    asm("{ .reg .u64 t; cvta.to.shared.u64 t, %1; cvt.u32.u64 %0, t; }"
        : "=r"(a) : "l"(p));
    return a;
}

__device__ __forceinline__ void ldmx4(uint32_t* r, uint32_t addr) {
    asm volatile("ldmatrix.sync.aligned.m8n8.x4.shared.b16 {%0,%1,%2,%3}, [%4];"
                 : "=r"(r[0]), "=r"(r[1]), "=r"(r[2]), "=r"(r[3]) : "r"(addr));
}

__device__ __forceinline__ void mma_bf16(float* c, const uint32_t* a,
                                         const uint32_t* b) {
    asm volatile(
        "mma.sync.aligned.m16n8k16.row.col.f32.bf16.bf16.f32 "
        "{%0,%1,%2,%3}, {%4,%5,%6,%7}, {%8,%9}, {%0,%1,%2,%3};"
        : "+f"(c[0]), "+f"(c[1]), "+f"(c[2]), "+f"(c[3])
        : "r"(a[0]), "r"(a[1]), "r"(a[2]), "r"(a[3]), "r"(b[0]), "r"(b[1]));
}

// ---------------------------------------------------------------------------
// Split fp32 -> (bf16 hi, bf16 lo)
// ---------------------------------------------------------------------------
__global__ __launch_bounds__(256) void split_bf16(
    const float* __restrict__ x, __nv_bfloat16* __restrict__ hi,
    __nv_bfloat16* __restrict__ lo, int n4)
{
    int i = blockIdx.x * blockDim.x + threadIdx.x;
    if (i >= n4) return;
    float4 v = ((const float4*)x)[i];
    __nv_bfloat16 h0 = __float2bfloat16(v.x);
    __nv_bfloat16 h1 = __float2bfloat16(v.y);
    __nv_bfloat16 h2 = __float2bfloat16(v.z);
    __nv_bfloat16 h3 = __float2bfloat16(v.w);
    __nv_bfloat16 l0 = __float2bfloat16(v.x - __bfloat162float(h0));
    __nv_bfloat16 l1 = __float2bfloat16(v.y - __bfloat162float(h1));
    __nv_bfloat16 l2 = __float2bfloat16(v.z - __bfloat162float(h2));
    __nv_bfloat16 l3 = __float2bfloat16(v.w - __bfloat162float(h3));
    __nv_bfloat162* hp = (__nv_bfloat162*)hi;
    __nv_bfloat162* lp = (__nv_bfloat162*)lo;
    hp[2 * i]     = __nv_bfloat162(h0, h1);
    hp[2 * i + 1] = __nv_bfloat162(h2, h3);
    lp[2 * i]     = __nv_bfloat162(l0, l1);
    lp[2 * i + 1] = __nv_bfloat162(l2, l3);
}

// ---------------------------------------------------------------------------
// HMMA GEMM:  C[M,N] = (Ahi+Alo)[M,K] @ (Whi+Wlo)[N,K]^T + bias
// 128x128 CTA tile, BK=32, 8 warps as 2(m) x 4(n), warp tile 64x32.
// 3-term bf16 error correction, fp32 accumulate.
// blockIdx.z selects one of up to 3 fused problems.
// ---------------------------------------------------------------------------
struct GemmP {
    const __nv_bfloat16 *ahi, *alo, *whi, *wlo;
    const float* bias;
    float* out;
};

#define GBK 32
#define GT_BYTES (128 * GBK * 2)   // 8192 B per tile

__global__ __launch_bounds__(256, 1) void gemm_hmma(GemmP p0, GemmP p1, GemmP p2)
{
    __shared__ char smem[4 * GT_BYTES];   // Ahi | Alo | Whi | Wlo

    GemmP p = (blockIdx.z == 0) ? p0 : (blockIdx.z == 1 ? p1 : p2);

    const int tid  = threadIdx.x;
    const int lane = tid & 31;
    const int wid  = tid >> 5;
    const int wm   = wid & 1;        // 0..1  -> m offset 64*wm
    const int wn   = wid >> 1;       // 0..3  -> n offset 32*wn
    const int bm   = blockIdx.y * 128;
    const int bn   = blockIdx.x * 128;

    const uint32_t sb  = smem_u32(smem);
    const uint32_t sAh = sb;
    const uint32_t sAl = sb + GT_BYTES;
    const uint32_t sWh = sb + 2 * GT_BYTES;
    const uint32_t sWl = sb + 3 * GT_BYTES;

    // ---- per-thread staging geometry: rows r0=tid>>2, r1=r0+64; unit u=tid&3
    const int u  = tid & 3;
    const int r0 = tid >> 2;
    const int r1 = r0 + 64;
    const uint32_t d0 = (uint32_t)(r0 * 64 + ((u ^ ((r0 >> 1) & 3)) << 4));
    const uint32_t d1 = (uint32_t)(r1 * 64 + ((u ^ ((r1 >> 1) & 3)) << 4));
    const size_t offA0 = (size_t)(bm + r0) * DM + u * 8;
    const size_t offA1 = (size_t)(bm + r1) * DM + u * 8;
    const size_t offW0 = (size_t)(bn + r0) * DM + u * 8;
    const size_t offW1 = (size_t)(bn + r1) * DM + u * 8;

    // ---- ldmatrix lane geometry
    const int sub = lane >> 3;
    // A (16x16 tile as 4 8x8 mats): rows 0-7/8-15 x k-units 0/1
    const int a_r16  = ((sub & 1) << 3) + (lane & 7);
    const int a_usel = sub >> 1;
    // W pair (two n8 tiles x 2 k-units)
    const int b_nt   = sub >> 1;        // which tile of the pair
    const int b_usel = sub & 1;
    const int b_r8   = lane & 7;

    int arow[4], asw[4];
    #pragma unroll
    for (int mt = 0; mt < 4; mt++) {
        const int gr = wm * 64 + mt * 16 + a_r16;
        arow[mt] = gr * 64;
        asw[mt]  = (gr >> 1) & 3;
    }
    int brow[2], bsw[2];
    #pragma unroll
    for (int j = 0; j < 2; j++) {
        const int nr = wn * 32 + (2 * j + b_nt) * 8 + b_r8;
        brow[j] = nr * 64;
        bsw[j]  = (nr >> 1) & 3;
    }

    float acc[4][4][4];
    #pragma unroll
    for (int mt = 0; mt < 4; mt++)
        #pragma unroll
        for (int nt = 0; nt < 4; nt++)
            #pragma unroll
            for (int r = 0; r < 4; r++) acc[mt][nt][r] = 0.f;

    // ---- prefetch chunk 0
    uint4 fAh0, fAh1, fAl0, fAl1, fWh0, fWh1, fWl0, fWl1;
    {
        fAh0 = *(const uint4*)(p.ahi + offA0); fAh1 = *(const uint4*)(p.ahi + offA1);
        fAl0 = *(const uint4*)(p.alo + offA0); fAl1 = *(const uint4*)(p.alo + offA1);
        fWh0 = *(const uint4*)(p.whi + offW0); fWh1 = *(const uint4*)(p.whi + offW1);
        fWl0 = *(const uint4*)(p.wlo + offW0); fWl1 = *(const uint4*)(p.wlo + offW1);
    }

    const int NCH = DM / GBK;   // 32
    for (int ch = 0; ch < NCH; ch++) {
        __syncthreads();
        *(uint4*)(smem + (sAh - sb) + d0) = fAh0;
        *(uint4*)(smem + (sAh - sb) + d1) = fAh1;
        *(uint4*)(smem + (sAl - sb) + d0) = fAl0;
        *(uint4*)(smem + (sAl - sb) + d1) = fAl1;
        *(uint4*)(smem + (sWh - sb) + d0) = fWh0;
        *(uint4*)(smem + (sWh - sb) + d1) = fWh1;
        *(uint4*)(smem + (sWl - sb) + d0) = fWl0;
        *(uint4*)(smem + (sWl - sb) + d1) = fWl1;
        __syncthreads();

        if (ch + 1 < NCH) {
            const int kb = (ch + 1) * GBK;
            fAh0 = *(const uint4*)(p.ahi + offA0 + kb);
            fAh1 = *(const uint4*)(p.ahi + offA1 + kb);
            fAl0 = *(const uint4*)(p.alo + offA0 + kb);
            fAl1 = *(const uint4*)(p.alo + offA1 + kb);
            fWh0 = *(const uint4*)(p.whi + offW0 + kb);
            fWh1 = *(const uint4*)(p.whi + offW1 + kb);
            fWl0 = *(const uint4*)(p.wlo + offW0 + kb);
            fWl1 = *(const uint4*)(p.wlo + offW1 + kb);
        }

        #pragma unroll
        for (int ks = 0; ks < 2; ks++) {
            uint32_t bh[4][2], bl[4][2];
            #pragma unroll
            for (int j = 0; j < 2; j++) {
                const uint32_t uoff =
                    (uint32_t)(((2 * ks + b_usel) ^ bsw[j]) << 4) + brow[j];
                ldmx4(&bh[2 * j][0], sWh + uoff);
                ldmx4(&bl[2 * j][0], sWl + uoff);
            }
            #pragma unroll
            for (int mt = 0; mt < 4; mt++) {
                uint32_t ah[4], al[4];
                const uint32_t uoff =
                    (uint32_t)(((2 * ks + a_usel) ^ asw[mt]) << 4) + arow[mt];
                ldmx4(ah, sAh + uoff);
                ldmx4(al, sAl + uoff);
                #pragma unroll
                for (int nt = 0; nt < 4; nt++) {
                    mma_bf16(acc[mt][nt], ah, bh[nt]);
                    mma_bf16(acc[mt][nt], ah, bl[nt]);
                    mma_bf16(acc[mt][nt], al, bh[nt]);
                }
            }
        }
    }

    // ---- epilogue: bias add, fp32 store
    #pragma unroll
    for (int mt = 0; mt < 4; mt++) {
        const int row0 = bm + wm * 64 + mt * 16 + (lane >> 2);
        #pragma unroll
        for (int nt = 0; nt < 4; nt++) {
            const int col = bn + wn * 32 + nt * 8 + (lane & 3) * 2;
            const float2 bv = *(const float2*)(p.bias + col);
            float2 o0, o1;
            o0.x = acc[mt][nt][0] + bv.x;
            o0.y = acc[mt][nt][1] + bv.y;
            o1.x = acc[mt][nt][2] + bv.x;
            o1.y = acc[mt][nt][3] + bv.y;
            *(float2*)(p.out + (size_t)row0 * DM + col)       = o0;
            *(float2*)(p.out + (size_t)(row0 + 8) * DM + col) = o1;
        }
    }
}

// ---------------------------------------------------------------------------
// Flash attention, fp32 (unchanged from R1 passing version).
// ---------------------------------------------------------------------------
#define BMQ 64
#define BNK 64
#define ATT_SMEM_FLOATS (64 * 64 + 3 * 64 * 65)

__global__ __launch_bounds__(256) void flash_attn(
    const float* __restrict__ Q, const float* __restrict__ K,
    const float* __restrict__ V, const int* __restrict__ mask,
    float* __restrict__ O)
{
    extern __shared__ float sm[];
    float* Qs = sm;
    float* Ks = Qs + 64 * 64;
    float* Vs = Ks + 64 * 65;
    float* Ps = Vs + 64 * 65;

    const int tid = threadIdx.x;
    const int tx  = tid & 15;
    const int ty  = tid >> 4;
    const int qb  = blockIdx.x;
    const int bh  = blockIdx.y;
    const int b   = bh >> 4;
    const int h   = bh & 15;
    const int q0  = qb * BMQ;
    const int rowbase = b * S_LEN;
    const int hoff = h * DK;

    const int i0 = ty * 4;
    const int cc = tx * 4;

    #pragma unroll
    for (int t = 0; t < 4; t++) {
        int f4 = tid + t * 256;
        int i  = f4 >> 4;
        int d4 = (f4 & 15) << 2;
        float4 v = *(const float4*)&Q[(size_t)(rowbase + q0 + i) * DM + hoff + d4];
        *(float4*)&Qs[i * 64 + d4] = v;
    }

    float m_i[4], l_i[4], o_acc[4][4];
    #pragma unroll
    for (int r = 0; r < 4; r++) {
        m_i[r] = -3.0e38f;
        l_i[r] = 0.f;
        #pragma unroll
        for (int c = 0; c < 4; c++) o_acc[r][c] = 0.f;
    }

    for (int kb = 0; kb < S_LEN / BNK; kb++) {
        const int k0g = kb * BNK;

        #pragma unroll
        for (int t = 0; t < 4; t++) {
            int f4 = tid + t * 256;
            int j  = f4 >> 4;
            int d4 = (f4 & 15) << 2;
            float4 kv = *(const float4*)&K[(size_t)(rowbase + k0g + j) * DM + hoff + d4];
            float4 vv = *(const float4*)&V[(size_t)(rowbase + k0g + j) * DM + hoff + d4];
            float* kd = &Ks[j * 65 + d4];
            kd[0] = kv.x; kd[1] = kv.y; kd[2] = kv.z; kd[3] = kv.w;
            float* vd = &Vs[j * 65 + d4];
            vd[0] = vv.x; vd[1] = vv.y; vd[2] = vv.z; vd[3] = vv.w;
        }
        __syncthreads();

        float s[4][4];
        #pragma unroll
        for (int r = 0; r < 4; r++)
            #pragma unroll
            for (int c = 0; c < 4; c++) s[r][c] = 0.f;

        #pragma unroll 8
        for (int d = 0; d < 64; d++) {
            float qv[4], kv[4];
            #pragma unroll
            for (int r = 0; r < 4; r++) qv[r] = Qs[(i0 + r) * 64 + d];
            #pragma unroll
            for (int c = 0; c < 4; c++) kv[c] = Ks[(cc + c) * 65 + d];
            #pragma unroll
            for (int r = 0; r < 4; r++)
                #pragma unroll
                for (int c = 0; c < 4; c++)
                    s[r][c] += qv[r] * kv[c];
        }

        #pragma unroll
        for (int r = 0; r < 4; r++) {
            const int qg = q0 + i0 + r;
            #pragma unroll
            for (int c = 0; c < 4; c++) {
                float sv = s[r][c] * 0.125f;
                int mv = mask[(size_t)qg * S_LEN + k0g + cc + c];
                s[r][c] = (mv == 0) ? -1e9f : sv;
            }
        }

        #pragma unroll
        for (int r = 0; r < 4; r++) {
            float rm = fmaxf(fmaxf(s[r][0], s[r][1]), fmaxf(s[r][2], s[r][3]));
            rm = fmaxf(rm, __shfl_xor_sync(0xffffffffu, rm, 1));
            rm = fmaxf(rm, __shfl_xor_sync(0xffffffffu, rm, 2));
            rm = fmaxf(rm, __shfl_xor_sync(0xffffffffu, rm, 4));
            rm = fmaxf(rm, __shfl_xor_sync(0xffffffffu, rm, 8));
            float mn = fmaxf(m_i[r], rm);
            float alpha = __expf(m_i[r] - mn);
            float rs = 0.f;
            #pragma unroll
            for (int c = 0; c < 4; c++) {
                s[r][c] = __expf(s[r][c] - mn);
                rs += s[r][c];
            }
            rs += __shfl_xor_sync(0xffffffffu, rs, 1);
            rs += __shfl_xor_sync(0xffffffffu, rs, 2);
            rs += __shfl_xor_sync(0xffffffffu, rs, 4);
            rs += __shfl_xor_sync(0xffffffffu, rs, 8);
            l_i[r] = l_i[r] * alpha + rs;
            m_i[r] = mn;
            #pragma unroll
            for (int c = 0; c < 4; c++) o_acc[r][c] *= alpha;
        }

        #pragma unroll
        for (int c = 0; c < 4; c++)
            #pragma unroll
            for (int r = 0; r < 4; r++)
                Ps[(cc + c) * 65 + i0 + r] = s[r][c];
        __syncthreads();

        #pragma unroll 8
        for (int j = 0; j < 64; j++) {
            float pv[4], vv[4];
            #pragma unroll
            for (int r = 0; r < 4; r++) pv[r] = Ps[j * 65 + i0 + r];
            #pragma unroll
            for (int c = 0; c < 4; c++) vv[c] = Vs[j * 65 + cc + c];
            #pragma unroll
            for (int r = 0; r < 4; r++)
                #pragma unroll
                for (int c = 0; c < 4; c++)
                    o_acc[r][c] += pv[r] * vv[c];
        }
        __syncthreads();
    }

    #pragma unroll
    for (int r = 0; r < 4; r++) {
        float inv = 1.f / l_i[r];
        float4 o;
        o.x = o_acc[r][0] * inv;
        o.y = o_acc[r][1] * inv;
        o.z = o_acc[r][2] * inv;
        o.w = o_acc[r][3] * inv;
        *(float4*)&O[(size_t)(rowbase + q0 + i0 + r) * DM + hoff + cc] = o;
    }
}

// ---------------------------------------------------------------------------
extern "C" void kernel_launch(void* const* d_in, const int* in_sizes, int n_in,
                              void* d_out, int out_size)
{
    const float* q    = (const float*)d_in[0];
    const float* k    = (const float*)d_in[1];
    const float* v    = (const float*)d_in[2];
    const int*   mask = (const int*)  d_in[3];
    const float* Wq   = (const float*)d_in[4];
    const float* bq   = (const float*)d_in[5];
    const float* Wk   = (const float*)d_in[6];
    const float* bk   = (const float*)d_in[7];
    const float* Wv   = (const float*)d_in[8];
    const float* bv   = (const float*)d_in[9];
    const float* Wo   = (const float*)d_in[10];
    const float* bo   = (const float*)d_in[11];
    float* out = (float*)d_out;

    float *gQ, *gK, *gV, *gAO;
    cudaGetSymbolAddress((void**)&gQ,  g_Q);
    cudaGetSymbolAddress((void**)&gK,  g_K);
    cudaGetSymbolAddress((void**)&gV,  g_V);
    cudaGetSymbolAddress((void**)&gAO, g_AO);

    __nv_bfloat16 *qh, *ql, *kh, *kl, *vh, *vl, *aoh, *aol;
    __nv_bfloat16 *wqh, *wql, *wkh, *wkl, *wvh, *wvl, *woh, *wol;
    cudaGetSymbolAddress((void**)&qh,  g_q_hi);  cudaGetSymbolAddress((void**)&ql,  g_q_lo);
    cudaGetSymbolAddress((void**)&kh,  g_k_hi);  cudaGetSymbolAddress((void**)&kl,  g_k_lo);
    cudaGetSymbolAddress((void**)&vh,  g_v_hi);  cudaGetSymbolAddress((void**)&vl,  g_v_lo);
    cudaGetSymbolAddress((void**)&aoh, g_ao_hi); cudaGetSymbolAddress((void**)&aol, g_ao_lo);
    cudaGetSymbolAddress((void**)&wqh, g_Wq_hi); cudaGetSymbolAddress((void**)&wql, g_Wq_lo);
    cudaGetSymbolAddress((void**)&wkh, g_Wk_hi); cudaGetSymbolAddress((void**)&wkl, g_Wk_lo);
    cudaGetSymbolAddress((void**)&wvh, g_Wv_hi); cudaGetSymbolAddress((void**)&wvl, g_Wv_lo);
    cudaGetSymbolAddress((void**)&woh, g_Wo_hi); cudaGetSymbolAddress((void**)&wol, g_Wo_lo);

    const int att_smem = ATT_SMEM_FLOATS * sizeof(float);
    cudaFuncSetAttribute(flash_attn, cudaFuncAttributeMaxDynamicSharedMemorySize,
                         att_smem);

    const int n4_in = MROWS * DM / 4;   // 1M float4
    const int n4_w  = DM * DM / 4;      // 256K float4

    // split inputs + weights to bf16 hi/lo
    split_bf16<<<n4_in / 256, 256>>>(q,  qh,  ql,  n4_in);
    split_bf16<<<n4_in / 256, 256>>>(k,  kh,  kl,  n4_in);
    split_bf16<<<n4_in / 256, 256>>>(v,  vh,  vl,  n4_in);
    split_bf16<<<n4_w  / 256, 256>>>(Wq, wqh, wql, n4_w);
    split_bf16<<<n4_w  / 256, 256>>>(Wk, wkh, wkl, n4_w);
    split_bf16<<<n4_w  / 256, 256>>>(Wv, wvh, wvl, n4_w);
    split_bf16<<<n4_w  / 256, 256>>>(Wo, woh, wol, n4_w);

    // fused Q/K/V projections (HMMA)
    GemmP pq = { qh, ql, wqh, wql, bq, gQ };
    GemmP pk = { kh, kl, wkh, wkl, bk, gK };
    GemmP pv = { vh, vl, wvh, wvl, bv, gV };
    dim3 gg3(DM / 128, MROWS / 128, 3);   // (8, 32, 3)
    gemm_hmma<<<gg3, 256>>>(pq, pk, pv);

    // attention (fp32)
    dim3 ga(S_LEN / BMQ, B_SZ * NH);      // (32, 32)
    flash_attn<<<ga, 256, att_smem>>>(gQ, gK, gV, mask, gAO);

    // split attention output, final projection (HMMA)
    split_bf16<<<n4_in / 256, 256>>>(gAO, aoh, aol, n4_in);
    GemmP po = { aoh, aol, woh, wol, bo, out };
    dim3 gg1(DM / 128, MROWS / 128, 1);
    gemm_hmma<<<gg1, 256>>>(po, po, po);
}

// round 5
// speedup vs baseline: 2.8991x; 2.0587x over previous
#include <cuda_runtime.h>
#include <cuda_bf16.h>
#include <cstdint>
#include <math.h>

#define S_LEN 2048
#define B_SZ  2
#define DM    1024
#define NH    16
#define DK    64
#define MROWS (B_SZ * S_LEN)   // 4096

// ---------------------------------------------------------------------------
// Scratch (static device memory; no allocations allowed)
// ---------------------------------------------------------------------------
// input splits
__device__ __nv_bfloat16 g_q_hi[MROWS * DM], g_q_lo[MROWS * DM];
__device__ __nv_bfloat16 g_k_hi[MROWS * DM], g_k_lo[MROWS * DM];
__device__ __nv_bfloat16 g_v_hi[MROWS * DM], g_v_lo[MROWS * DM];
__device__ __nv_bfloat16 g_Wq_hi[DM * DM], g_Wq_lo[DM * DM];
__device__ __nv_bfloat16 g_Wk_hi[DM * DM], g_Wk_lo[DM * DM];
__device__ __nv_bfloat16 g_Wv_hi[DM * DM], g_Wv_lo[DM * DM];
__device__ __nv_bfloat16 g_Wo_hi[DM * DM], g_Wo_lo[DM * DM];
// projected Q/K/V (hi/lo) and attention output (hi/lo)
__device__ __nv_bfloat16 g_Qph[MROWS * DM], g_Qpl[MROWS * DM];
__device__ __nv_bfloat16 g_Kph[MROWS * DM], g_Kpl[MROWS * DM];
__device__ __nv_bfloat16 g_Vph[MROWS * DM], g_Vpl[MROWS * DM];
__device__ __nv_bfloat16 g_AOh[MROWS * DM], g_AOl[MROWS * DM];
// mask all-ones flag
__device__ int g_mask_ones;

// ---------------------------------------------------------------------------
// HMMA helpers (base sm_100 target: mma.sync + ldmatrix)
// ---------------------------------------------------------------------------
__device__ __forceinline__ uint32_t smem_u32(const void* p) {
    uint32_t a;
    asm("{ .reg .u64 t; cvta.to.shared.u64 t, %1; cvt.u32.u64 %0, t; }"
        : "=r"(a) : "l"(p));
    return a;
}

__device__ __forceinline__ void ldmx4(uint32_t* r, uint32_t addr) {
    asm volatile("ldmatrix.sync.aligned.m8n8.x4.shared.b16 {%0,%1,%2,%3}, [%4];"
                 : "=r"(r[0]), "=r"(r[1]), "=r"(r[2]), "=r"(r[3]) : "r"(addr));
}

__device__ __forceinline__ void ldmx4t(uint32_t* r, uint32_t addr) {
    asm volatile("ldmatrix.sync.aligned.m8n8.x4.trans.shared.b16 {%0,%1,%2,%3}, [%4];"
                 : "=r"(r[0]), "=r"(r[1]), "=r"(r[2]), "=r"(r[3]) : "r"(addr));
}

__device__ __forceinline__ void mma_bf16(float* c, const uint32_t* a,
                                         const uint32_t* b) {
    asm volatile(
        "mma.sync.aligned.m16n8k16.row.col.f32.bf16.bf16.f32 "
        "{%0,%1,%2,%3}, {%4,%5,%6,%7}, {%8,%9}, {%0,%1,%2,%3};"
        : "+f"(c[0]), "+f"(c[1]), "+f"(c[2]), "+f"(c[3])
        : "r"(a[0]), "r"(a[1]), "r"(a[2]), "r"(a[3]), "r"(b[0]), "r"(b[1]));
}

// pack (x,y) -> bf16x2 hi bits; residual -> bf16x2 lo bits
__device__ __forceinline__ uint32_t split2(float x, float y, uint32_t& lo) {
    __nv_bfloat16 hx = __float2bfloat16(x), hy = __float2bfloat16(y);
    __nv_bfloat16 lx = __float2bfloat16(x - __bfloat162float(hx));
    __nv_bfloat16 ly = __float2bfloat16(y - __bfloat162float(hy));
    __nv_bfloat162 h(hx, hy), l(lx, ly);
    lo = *reinterpret_cast<uint32_t*>(&l);
    return *reinterpret_cast<uint32_t*>(&h);
}

// ---------------------------------------------------------------------------
// Mask all-ones detection
// ---------------------------------------------------------------------------
__global__ void reset_flag() { g_mask_ones = 1; }

__global__ __launch_bounds__(256) void check_mask(const int* __restrict__ m, int n) {
    int i = blockIdx.x * blockDim.x + threadIdx.x;
    int ok = 1;
    for (; i < n; i += gridDim.x * blockDim.x) ok &= (m[i] != 0);
    ok = __all_sync(0xffffffffu, ok);
    if ((threadIdx.x & 31) == 0 && !ok) atomicExch(&g_mask_ones, 0);
}

// ---------------------------------------------------------------------------
// Split fp32 -> (bf16 hi, bf16 lo)
// ---------------------------------------------------------------------------
__global__ __launch_bounds__(256) void split_bf16(
    const float* __restrict__ x, __nv_bfloat16* __restrict__ hi,
    __nv_bfloat16* __restrict__ lo, int n4)
{
    int i = blockIdx.x * blockDim.x + threadIdx.x;
    if (i >= n4) return;
    float4 v = ((const float4*)x)[i];
    uint32_t l0, l1, h0, h1;
    h0 = split2(v.x, v.y, l0);
    h1 = split2(v.z, v.w, l1);
    uint32_t* hp = (uint32_t*)hi;
    uint32_t* lp = (uint32_t*)lo;
    hp[2 * i] = h0; hp[2 * i + 1] = h1;
    lp[2 * i] = l0; lp[2 * i + 1] = l1;
}

// ---------------------------------------------------------------------------
// HMMA GEMM:  C[M,N] = (Ahi+Alo)[M,K] @ (Whi+Wlo)[N,K]^T + bias
// 128x128 CTA tile, BK=32, 8 warps as 2(m) x 4(n). 3-term correction.
// Output either fp32 (outf) or bf16 hi/lo (outh/outl).
// ---------------------------------------------------------------------------
struct GemmP {
    const __nv_bfloat16 *ahi, *alo, *whi, *wlo;
    const float* bias;
    float* outf;
    __nv_bfloat16 *outh, *outl;
};

#define GBK 32
#define GT_BYTES (128 * GBK * 2)   // 8192 B per tile

__global__ __launch_bounds__(256, 1) void gemm_hmma(GemmP p0, GemmP p1, GemmP p2)
{
    __shared__ char smem[4 * GT_BYTES];   // Ahi | Alo | Whi | Wlo

    GemmP p = (blockIdx.z == 0) ? p0 : (blockIdx.z == 1 ? p1 : p2);

    const int tid  = threadIdx.x;
    const int lane = tid & 31;
    const int wid  = tid >> 5;
    const int wm   = wid & 1;
    const int wn   = wid >> 1;
    const int bm   = blockIdx.y * 128;
    const int bn   = blockIdx.x * 128;

    const uint32_t sb  = smem_u32(smem);
    const uint32_t sAh = sb;
    const uint32_t sAl = sb + GT_BYTES;
    const uint32_t sWh = sb + 2 * GT_BYTES;
    const uint32_t sWl = sb + 3 * GT_BYTES;

    const int u  = tid & 3;
    const int r0 = tid >> 2;
    const int r1 = r0 + 64;
    const uint32_t d0 = (uint32_t)(r0 * 64 + ((u ^ ((r0 >> 1) & 3)) << 4));
    const uint32_t d1 = (uint32_t)(r1 * 64 + ((u ^ ((r1 >> 1) & 3)) << 4));
    const size_t offA0 = (size_t)(bm + r0) * DM + u * 8;
    const size_t offA1 = (size_t)(bm + r1) * DM + u * 8;
    const size_t offW0 = (size_t)(bn + r0) * DM + u * 8;
    const size_t offW1 = (size_t)(bn + r1) * DM + u * 8;

    const int sub = lane >> 3;
    const int a_r16  = ((sub & 1) << 3) + (lane & 7);
    const int a_usel = sub >> 1;
    const int b_nt   = sub >> 1;
    const int b_usel = sub & 1;
    const int b_r8   = lane & 7;

    int arow[4], asw[4];
    #pragma unroll
    for (int mt = 0; mt < 4; mt++) {
        const int gr = wm * 64 + mt * 16 + a_r16;
        arow[mt] = gr * 64;
        asw[mt]  = (gr >> 1) & 3;
    }
    int brow[2], bsw[2];
    #pragma unroll
    for (int j = 0; j < 2; j++) {
        const int nr = wn * 32 + (2 * j + b_nt) * 8 + b_r8;
        brow[j] = nr * 64;
        bsw[j]  = (nr >> 1) & 3;
    }

    float acc[4][4][4];
    #pragma unroll
    for (int mt = 0; mt < 4; mt++)
        #pragma unroll
        for (int nt = 0; nt < 4; nt++)
            #pragma unroll
            for (int r = 0; r < 4; r++) acc[mt][nt][r] = 0.f;

    uint4 fAh0, fAh1, fAl0, fAl1, fWh0, fWh1, fWl0, fWl1;
    fAh0 = *(const uint4*)(p.ahi + offA0); fAh1 = *(const uint4*)(p.ahi + offA1);
    fAl0 = *(const uint4*)(p.alo + offA0); fAl1 = *(const uint4*)(p.alo + offA1);
    fWh0 = *(const uint4*)(p.whi + offW0); fWh1 = *(const uint4*)(p.whi + offW1);
    fWl0 = *(const uint4*)(p.wlo + offW0); fWl1 = *(const uint4*)(p.wlo + offW1);

    const int NCH = DM / GBK;   // 32
    for (int ch = 0; ch < NCH; ch++) {
        __syncthreads();
        *(uint4*)(smem + (sAh - sb) + d0) = fAh0;
        *(uint4*)(smem + (sAh - sb) + d1) = fAh1;
        *(uint4*)(smem + (sAl - sb) + d0) = fAl0;
        *(uint4*)(smem + (sAl - sb) + d1) = fAl1;
        *(uint4*)(smem + (sWh - sb) + d0) = fWh0;
        *(uint4*)(smem + (sWh - sb) + d1) = fWh1;
        *(uint4*)(smem + (sWl - sb) + d0) = fWl0;
        *(uint4*)(smem + (sWl - sb) + d1) = fWl1;
        __syncthreads();

        if (ch + 1 < NCH) {
            const int kb = (ch + 1) * GBK;
            fAh0 = *(const uint4*)(p.ahi + offA0 + kb);
            fAh1 = *(const uint4*)(p.ahi + offA1 + kb);
            fAl0 = *(const uint4*)(p.alo + offA0 + kb);
            fAl1 = *(const uint4*)(p.alo + offA1 + kb);
            fWh0 = *(const uint4*)(p.whi + offW0 + kb);
            fWh1 = *(const uint4*)(p.whi + offW1 + kb);
            fWl0 = *(const uint4*)(p.wlo + offW0 + kb);
            fWl1 = *(const uint4*)(p.wlo + offW1 + kb);
        }

        #pragma unroll
        for (int ks = 0; ks < 2; ks++) {
            uint32_t bh[4][2], bl[4][2];
            #pragma unroll
            for (int j = 0; j < 2; j++) {
                const uint32_t uoff =
                    (uint32_t)(((2 * ks + b_usel) ^ bsw[j]) << 4) + brow[j];
                ldmx4(&bh[2 * j][0], sWh + uoff);
                ldmx4(&bl[2 * j][0], sWl + uoff);
            }
            #pragma unroll
            for (int mt = 0; mt < 4; mt++) {
                uint32_t ah[4], al[4];
                const uint32_t uoff =
                    (uint32_t)(((2 * ks + a_usel) ^ asw[mt]) << 4) + arow[mt];
                ldmx4(ah, sAh + uoff);
                ldmx4(al, sAl + uoff);
                #pragma unroll
                for (int nt = 0; nt < 4; nt++) {
                    mma_bf16(acc[mt][nt], ah, bh[nt]);
                    mma_bf16(acc[mt][nt], ah, bl[nt]);
                    mma_bf16(acc[mt][nt], al, bh[nt]);
                }
            }
        }
    }

    // ---- epilogue: bias add, then fp32 or bf16 hi/lo store
    #pragma unroll
    for (int mt = 0; mt < 4; mt++) {
        const int row0 = bm + wm * 64 + mt * 16 + (lane >> 2);
        #pragma unroll
        for (int nt = 0; nt < 4; nt++) {
            const int col = bn + wn * 32 + nt * 8 + (lane & 3) * 2;
            const float2 bv = *(const float2*)(p.bias + col);
            float x0 = acc[mt][nt][0] + bv.x;
            float y0 = acc[mt][nt][1] + bv.y;
            float x1 = acc[mt][nt][2] + bv.x;
            float y1 = acc[mt][nt][3] + bv.y;
            if (p.outf) {
                *(float2*)(p.outf + (size_t)row0 * DM + col)       = make_float2(x0, y0);
                *(float2*)(p.outf + (size_t)(row0 + 8) * DM + col) = make_float2(x1, y1);
            } else {
                uint32_t l0, l1;
                uint32_t h0 = split2(x0, y0, l0);
                uint32_t h1 = split2(x1, y1, l1);
                *(uint32_t*)(p.outh + (size_t)row0 * DM + col)       = h0;
                *(uint32_t*)(p.outl + (size_t)row0 * DM + col)       = l0;
                *(uint32_t*)(p.outh + (size_t)(row0 + 8) * DM + col) = h1;
                *(uint32_t*)(p.outl + (size_t)(row0 + 8) * DM + col) = l1;
            }
        }
    }
}

// ---------------------------------------------------------------------------
// Flash attention with HMMA (3-term bf16 error correction both GEMMs).
// CTA = 128 queries x one (b,h); 8 warps, warp = m16; KV block = 64.
// smem 64KB: Qh,Ql[128x64] Kh,Kl[64x64] Vh,Vl[64x64], 128B rows, u^(r&7) swizzle.
// ---------------------------------------------------------------------------
#define ATT_SMEM (64 * 1024)

__global__ __launch_bounds__(256, 2) void flash_attn_mma(
    const __nv_bfloat16* __restrict__ Qh, const __nv_bfloat16* __restrict__ Ql,
    const __nv_bfloat16* __restrict__ Kh, const __nv_bfloat16* __restrict__ Kl,
    const __nv_bfloat16* __restrict__ Vh, const __nv_bfloat16* __restrict__ Vl,
    const int* __restrict__ mask,
    __nv_bfloat16* __restrict__ Oh, __nv_bfloat16* __restrict__ Ol)
{
    extern __shared__ char sm[];
    const uint32_t sb  = smem_u32(sm);
    const uint32_t sQh = sb,          sQl = sb + 16384;
    const uint32_t sKh = sb + 32768,  sKl = sb + 40960;
    const uint32_t sVh = sb + 49152,  sVl = sb + 57344;

    const int tid  = threadIdx.x;
    const int lane = tid & 31;
    const int wid  = tid >> 5;
    const int qb   = blockIdx.x;
    const int bh   = blockIdx.y;
    const int b    = bh >> 4;
    const int h    = bh & 15;
    const int q0   = qb * 128;
    const int rowbase = b * S_LEN;
    const int hoff = h * DK;
    const int allones = g_mask_ones;

    // ---- load Q tile (128 x 64 hi/lo), swizzled
    #pragma unroll
    for (int t = 0; t < 4; t++) {
        const int idx = tid + t * 256;      // 0..1023
        const int r = idx >> 3, uu = idx & 7;
        const size_t g = (size_t)(rowbase + q0 + r) * DM + hoff + uu * 8;
        const uint32_t d = (uint32_t)(r * 128 + ((uu ^ (r & 7)) << 4));
        *(uint4*)(sm + (sQh - sb) + d) = *(const uint4*)(Qh + g);
        *(uint4*)(sm + (sQl - sb) + d) = *(const uint4*)(Ql + g);
    }

    // lane geometry
    const int sub = lane >> 3, l7 = lane & 7;
    const int a_r  = ((sub & 1) << 3) + l7;    // A row-in-tile
    const int a_us = sub >> 1;                 // A k-unit select
    const int b_nt = sub >> 1, b_us = sub & 1; // B (K) geometry
    const int qrow = wid * 16 + a_r;           // Q smem row for this lane
    const int vro  = ((sub & 1) << 3) + l7;    // V token row-in-ktile
    const int vus  = sub >> 1;                 // V unit select

    float o[8][4];
    #pragma unroll
    for (int nt = 0; nt < 8; nt++)
        #pragma unroll
        for (int e = 0; e < 4; e++) o[nt][e] = 0.f;
    float m0 = -3.0e38f, m1 = -3.0e38f, l0 = 0.f, l1 = 0.f;

    for (int kb = 0; kb < S_LEN / 64; kb++) {
        const int k0g = kb * 64;

        // ---- load K/V tiles (64 x 64 hi/lo each)
        #pragma unroll
        for (int t = 0; t < 2; t++) {
            const int idx = tid + t * 256;   // 0..511
            const int r = idx >> 3, uu = idx & 7;
            const size_t g = (size_t)(rowbase + k0g + r) * DM + hoff + uu * 8;
            const uint32_t d = (uint32_t)(r * 128 + ((uu ^ (r & 7)) << 4));
            *(uint4*)(sm + (sKh - sb) + d) = *(const uint4*)(Kh + g);
            *(uint4*)(sm + (sKl - sb) + d) = *(const uint4*)(Kl + g);
            *(uint4*)(sm + (sVh - sb) + d) = *(const uint4*)(Vh + g);
            *(uint4*)(sm + (sVl - sb) + d) = *(const uint4*)(Vl + g);
        }
        __syncthreads();

        // ---- S = Q K^T (3-term)
        float c[8][4];
        #pragma unroll
        for (int j = 0; j < 8; j++)
            #pragma unroll
            for (int e = 0; e < 4; e++) c[j][e] = 0.f;

        #pragma unroll
        for (int ks = 0; ks < 4; ks++) {
            uint32_t ah[4], al[4];
            const uint32_t ua = (uint32_t)((((2 * ks + a_us) ^ (qrow & 7)) << 4) + qrow * 128);
            ldmx4(ah, sQh + ua);
            ldmx4(al, sQl + ua);
            #pragma unroll
            for (int jp = 0; jp < 4; jp++) {
                uint32_t bhf[4], blf[4];
                const int nr = jp * 16 + b_nt * 8 + l7;
                const uint32_t ub = (uint32_t)((((2 * ks + b_us) ^ (nr & 7)) << 4) + nr * 128);
                ldmx4(bhf, sKh + ub);
                ldmx4(blf, sKl + ub);
                mma_bf16(c[2 * jp],     ah, bhf);
                mma_bf16(c[2 * jp],     ah, blf);
                mma_bf16(c[2 * jp],     al, bhf);
                mma_bf16(c[2 * jp + 1], ah, bhf + 2);
                mma_bf16(c[2 * jp + 1], ah, blf + 2);
                mma_bf16(c[2 * jp + 1], al, bhf + 2);
            }
        }

        // ---- scale + mask
        if (allones) {
            #pragma unroll
            for (int j = 0; j < 8; j++)
                #pragma unroll
                for (int e = 0; e < 4; e++) c[j][e] *= 0.125f;
        } else {
            const int qg0 = q0 + wid * 16 + (lane >> 2);
            #pragma unroll
            for (int j = 0; j < 8; j++) {
                const int colb = k0g + j * 8 + 2 * (lane & 3);
                #pragma unroll
                for (int e = 0; e < 4; e++) {
                    const int qq = (e < 2) ? qg0 : qg0 + 8;
                    const int kk = colb + (e & 1);
                    const int mv = mask[(size_t)qq * S_LEN + kk];
                    c[j][e] = mv ? c[j][e] * 0.125f : -1e9f;
                }
            }
        }

        // ---- online softmax update
        float rm0 = -3.0e38f, rm1 = -3.0e38f;
        #pragma unroll
        for (int j = 0; j < 8; j++) {
            rm0 = fmaxf(rm0, fmaxf(c[j][0], c[j][1]));
            rm1 = fmaxf(rm1, fmaxf(c[j][2], c[j][3]));
        }
        rm0 = fmaxf(rm0, __shfl_xor_sync(0xffffffffu, rm0, 1));
        rm0 = fmaxf(rm0, __shfl_xor_sync(0xffffffffu, rm0, 2));
        rm1 = fmaxf(rm1, __shfl_xor_sync(0xffffffffu, rm1, 1));
        rm1 = fmaxf(rm1, __shfl_xor_sync(0xffffffffu, rm1, 2));
        const float mn0 = fmaxf(m0, rm0), mn1 = fmaxf(m1, rm1);
        const float al0 = __expf(m0 - mn0), al1 = __expf(m1 - mn1);
        float rs0 = 0.f, rs1 = 0.f;
        #pragma unroll
        for (int j = 0; j < 8; j++) {
            c[j][0] = __expf(c[j][0] - mn0);
            c[j][1] = __expf(c[j][1] - mn0);
            c[j][2] = __expf(c[j][2] - mn1);
            c[j][3] = __expf(c[j][3] - mn1);
            rs0 += c[j][0] + c[j][1];
            rs1 += c[j][2] + c[j][3];
        }
        rs0 += __shfl_xor_sync(0xffffffffu, rs0, 1);
        rs0 += __shfl_xor_sync(0xffffffffu, rs0, 2);
        rs1 += __shfl_xor_sync(0xffffffffu, rs1, 1);
        rs1 += __shfl_xor_sync(0xffffffffu, rs1, 2);
        l0 = l0 * al0 + rs0;
        l1 = l1 * al1 + rs1;
        m0 = mn0; m1 = mn1;
        #pragma unroll
        for (int nt = 0; nt < 8; nt++) {
            o[nt][0] *= al0; o[nt][1] *= al0;
            o[nt][2] *= al1; o[nt][3] *= al1;
        }

        // ---- O += P V (3-term); P packed register-locally from c
        #pragma unroll
        for (int kt = 0; kt < 4; kt++) {
            uint32_t ph[4], pl[4];
            ph[0] = split2(c[2 * kt][0],     c[2 * kt][1],     pl[0]);
            ph[1] = split2(c[2 * kt][2],     c[2 * kt][3],     pl[1]);
            ph[2] = split2(c[2 * kt + 1][0], c[2 * kt + 1][1], pl[2]);
            ph[3] = split2(c[2 * kt + 1][2], c[2 * kt + 1][3], pl[3]);

            const int tv = kt * 16 + vro;
            #pragma unroll
            for (int dp = 0; dp < 4; dp++) {
                uint32_t vh4[4], vl4[4];
                const uint32_t uv = (uint32_t)((((2 * dp + vus) ^ (tv & 7)) << 4) + tv * 128);
                ldmx4t(vh4, sVh + uv);
                ldmx4t(vl4, sVl + uv);
                mma_bf16(o[2 * dp],     ph, vh4);
                mma_bf16(o[2 * dp],     ph, vl4);
                mma_bf16(o[2 * dp],     pl, vh4);
                mma_bf16(o[2 * dp + 1], ph, vh4 + 2);
                mma_bf16(o[2 * dp + 1], ph, vl4 + 2);
                mma_bf16(o[2 * dp + 1], pl, vh4 + 2);
            }
        }
        __syncthreads();
    }

    // ---- epilogue: O / l -> bf16 hi/lo
    const float inv0 = 1.f / l0, inv1 = 1.f / l1;
    const int gr0 = rowbase + q0 + wid * 16 + (lane >> 2);
    #pragma unroll
    for (int nt = 0; nt < 8; nt++) {
        const int col = hoff + nt * 8 + 2 * (lane & 3);
        uint32_t lo0, lo1;
        const uint32_t h0 = split2(o[nt][0] * inv0, o[nt][1] * inv0, lo0);
        const uint32_t h1 = split2(o[nt][2] * inv1, o[nt][3] * inv1, lo1);
        *(uint32_t*)(Oh + (size_t)gr0 * DM + col)       = h0;
        *(uint32_t*)(Ol + (size_t)gr0 * DM + col)       = lo0;
        *(uint32_t*)(Oh + (size_t)(gr0 + 8) * DM + col) = h1;
        *(uint32_t*)(Ol + (size_t)(gr0 + 8) * DM + col) = lo1;
    }
}

// ---------------------------------------------------------------------------
extern "C" void kernel_launch(void* const* d_in, const int* in_sizes, int n_in,
                              void* d_out, int out_size)
{
    const float* q    = (const float*)d_in[0];
    const float* k    = (const float*)d_in[1];
    const float* v    = (const float*)d_in[2];
    const int*   mask = (const int*)  d_in[3];
    const float* Wq   = (const float*)d_in[4];
    const float* bq   = (const float*)d_in[5];
    const float* Wk   = (const float*)d_in[6];
    const float* bk   = (const float*)d_in[7];
    const float* Wv   = (const float*)d_in[8];
    const float* bv   = (const float*)d_in[9];
    const float* Wo   = (const float*)d_in[10];
    const float* bo   = (const float*)d_in[11];
    float* out = (float*)d_out;

    __nv_bfloat16 *qh, *ql, *kh, *kl, *vh, *vl;
    __nv_bfloat16 *wqh, *wql, *wkh, *wkl, *wvh, *wvl, *woh, *wol;
    __nv_bfloat16 *Qph, *Qpl, *Kph, *Kpl, *Vph, *Vpl, *AOh, *AOl;
    cudaGetSymbolAddress((void**)&qh,  g_q_hi);  cudaGetSymbolAddress((void**)&ql,  g_q_lo);
    cudaGetSymbolAddress((void**)&kh,  g_k_hi);  cudaGetSymbolAddress((void**)&kl,  g_k_lo);
    cudaGetSymbolAddress((void**)&vh,  g_v_hi);  cudaGetSymbolAddress((void**)&vl,  g_v_lo);
    cudaGetSymbolAddress((void**)&wqh, g_Wq_hi); cudaGetSymbolAddress((void**)&wql, g_Wq_lo);
    cudaGetSymbolAddress((void**)&wkh, g_Wk_hi); cudaGetSymbolAddress((void**)&wkl, g_Wk_lo);
    cudaGetSymbolAddress((void**)&wvh, g_Wv_hi); cudaGetSymbolAddress((void**)&wvl, g_Wv_lo);
    cudaGetSymbolAddress((void**)&woh, g_Wo_hi); cudaGetSymbolAddress((void**)&wol, g_Wo_lo);
    cudaGetSymbolAddress((void**)&Qph, g_Qph);   cudaGetSymbolAddress((void**)&Qpl, g_Qpl);
    cudaGetSymbolAddress((void**)&Kph, g_Kph);   cudaGetSymbolAddress((void**)&Kpl, g_Kpl);
    cudaGetSymbolAddress((void**)&Vph, g_Vph);   cudaGetSymbolAddress((void**)&Vpl, g_Vpl);
    cudaGetSymbolAddress((void**)&AOh, g_AOh);   cudaGetSymbolAddress((void**)&AOl, g_AOl);

    cudaFuncSetAttribute(flash_attn_mma, cudaFuncAttributeMaxDynamicSharedMemorySize,
                         ATT_SMEM);

    const int n4_in = MROWS * DM / 4;
    const int n4_w  = DM * DM / 4;

    // mask all-ones check
    reset_flag<<<1, 1>>>();
    check_mask<<<1024, 256>>>(mask, S_LEN * S_LEN);

    // split inputs + weights to bf16 hi/lo
    split_bf16<<<n4_in / 256, 256>>>(q,  qh,  ql,  n4_in);
    split_bf16<<<n4_in / 256, 256>>>(k,  kh,  kl,  n4_in);
    split_bf16<<<n4_in / 256, 256>>>(v,  vh,  vl,  n4_in);
    split_bf16<<<n4_w  / 256, 256>>>(Wq, wqh, wql, n4_w);
    split_bf16<<<n4_w  / 256, 256>>>(Wk, wkh, wkl, n4_w);
    split_bf16<<<n4_w  / 256, 256>>>(Wv, wvh, wvl, n4_w);
    split_bf16<<<n4_w  / 256, 256>>>(Wo, woh, wol, n4_w);

    // fused Q/K/V projections -> bf16 hi/lo outputs
    GemmP pq = { qh, ql, wqh, wql, bq, nullptr, Qph, Qpl };
    GemmP pk = { kh, kl, wkh, wkl, bk, nullptr, Kph, Kpl };
    GemmP pv = { vh, vl, wvh, wvl, bv, nullptr, Vph, Vpl };
    dim3 gg3(DM / 128, MROWS / 128, 3);
    gemm_hmma<<<gg3, 256>>>(pq, pk, pv);

    // attention (HMMA) -> AO hi/lo
    dim3 ga(S_LEN / 128, B_SZ * NH);   // (16, 32)
    flash_attn_mma<<<ga, 256, ATT_SMEM>>>(Qph, Qpl, Kph, Kpl, Vph, Vpl, mask,
                                          AOh, AOl);

    // final projection -> fp32 out
    GemmP po = { AOh, AOl, woh, wol, bo, out, nullptr, nullptr };
    dim3 gg1(DM / 128, MROWS / 128, 1);
    gemm_hmma<<<gg1, 256>>>(po, po, po);
}

// round 6
// speedup vs baseline: 2.9031x; 1.0014x over previous
#include <cuda_runtime.h>
#include <cuda_bf16.h>
#include <cstdint>
#include <math.h>

#define S_LEN 2048
#define B_SZ  2
#define DM    1024
#define NH    16
#define DK    64
#define MROWS (B_SZ * S_LEN)   // 4096

// ---------------------------------------------------------------------------
// Scratch (static device memory; no allocations allowed)
// ---------------------------------------------------------------------------
// input splits
__device__ __nv_bfloat16 g_q_hi[MROWS * DM], g_q_lo[MROWS * DM];
__device__ __nv_bfloat16 g_k_hi[MROWS * DM], g_k_lo[MROWS * DM];
__device__ __nv_bfloat16 g_v_hi[MROWS * DM], g_v_lo[MROWS * DM];
__device__ __nv_bfloat16 g_Wq_hi[DM * DM], g_Wq_lo[DM * DM];
__device__ __nv_bfloat16 g_Wk_hi[DM * DM], g_Wk_lo[DM * DM];
__device__ __nv_bfloat16 g_Wv_hi[DM * DM], g_Wv_lo[DM * DM];
__device__ __nv_bfloat16 g_Wo_hi[DM * DM], g_Wo_lo[DM * DM];
// projected Q/K/V (hi/lo) and attention output (hi/lo)
__device__ __nv_bfloat16 g_Qph[MROWS * DM], g_Qpl[MROWS * DM];
__device__ __nv_bfloat16 g_Kph[MROWS * DM], g_Kpl[MROWS * DM];
__device__ __nv_bfloat16 g_Vph[MROWS * DM], g_Vpl[MROWS * DM];
__device__ __nv_bfloat16 g_AOh[MROWS * DM], g_AOl[MROWS * DM];
// mask all-ones flag
__device__ int g_mask_ones;

// ---------------------------------------------------------------------------
// HMMA helpers (base sm_100 target: mma.sync + ldmatrix)
// ---------------------------------------------------------------------------
__device__ __forceinline__ uint32_t smem_u32(const void* p) {
    uint32_t a;
    asm("{ .reg .u64 t; cvta.to.shared.u64 t, %1; cvt.u32.u64 %0, t; }"
        : "=r"(a) : "l"(p));
    return a;
}

__device__ __forceinline__ void ldmx4(uint32_t* r, uint32_t addr) {
    asm volatile("ldmatrix.sync.aligned.m8n8.x4.shared.b16 {%0,%1,%2,%3}, [%4];"
                 : "=r"(r[0]), "=r"(r[1]), "=r"(r[2]), "=r"(r[3]) : "r"(addr));
}

__device__ __forceinline__ void ldmx4t(uint32_t* r, uint32_t addr) {
    asm volatile("ldmatrix.sync.aligned.m8n8.x4.trans.shared.b16 {%0,%1,%2,%3}, [%4];"
                 : "=r"(r[0]), "=r"(r[1]), "=r"(r[2]), "=r"(r[3]) : "r"(addr));
}

__device__ __forceinline__ void mma_bf16(float* c, const uint32_t* a,
                                         const uint32_t* b) {
    asm volatile(
        "mma.sync.aligned.m16n8k16.row.col.f32.bf16.bf16.f32 "
        "{%0,%1,%2,%3}, {%4,%5,%6,%7}, {%8,%9}, {%0,%1,%2,%3};"
        : "+f"(c[0]), "+f"(c[1]), "+f"(c[2]), "+f"(c[3])
        : "r"(a[0]), "r"(a[1]), "r"(a[2]), "r"(a[3]), "r"(b[0]), "r"(b[1]));
}

// pack (x,y) -> bf16x2 hi bits; residual -> bf16x2 lo bits
__device__ __forceinline__ uint32_t split2(float x, float y, uint32_t& lo) {
    __nv_bfloat16 hx = __float2bfloat16(x), hy = __float2bfloat16(y);
    __nv_bfloat16 lx = __float2bfloat16(x - __bfloat162float(hx));
    __nv_bfloat16 ly = __float2bfloat16(y - __bfloat162float(hy));
    __nv_bfloat162 h(hx, hy), l(lx, ly);
    lo = *reinterpret_cast<uint32_t*>(&l);
    return *reinterpret_cast<uint32_t*>(&h);
}

// ---------------------------------------------------------------------------
// Mask all-ones detection
// ---------------------------------------------------------------------------
__global__ void reset_flag() { g_mask_ones = 1; }

__global__ __launch_bounds__(256) void check_mask(const int* __restrict__ m, int n) {
    int i = blockIdx.x * blockDim.x + threadIdx.x;
    int ok = 1;
    for (; i < n; i += gridDim.x * blockDim.x) ok &= (m[i] != 0);
    ok = __all_sync(0xffffffffu, ok);
    if ((threadIdx.x & 31) == 0 && !ok) atomicExch(&g_mask_ones, 0);
}

// ---------------------------------------------------------------------------
// Split fp32 -> (bf16 hi, bf16 lo)
// ---------------------------------------------------------------------------
__global__ __launch_bounds__(256) void split_bf16(
    const float* __restrict__ x, __nv_bfloat16* __restrict__ hi,
    __nv_bfloat16* __restrict__ lo, int n4)
{
    int i = blockIdx.x * blockDim.x + threadIdx.x;
    if (i >= n4) return;
    float4 v = ((const float4*)x)[i];
    uint32_t l0, l1, h0, h1;
    h0 = split2(v.x, v.y, l0);
    h1 = split2(v.z, v.w, l1);
    uint32_t* hp = (uint32_t*)hi;
    uint32_t* lp = (uint32_t*)lo;
    hp[2 * i] = h0; hp[2 * i + 1] = h1;
    lp[2 * i] = l0; lp[2 * i + 1] = l1;
}

// ---------------------------------------------------------------------------
// HMMA GEMM:  C[M,N] = (Ahi+Alo)[M,K] @ (Whi+Wlo)[N,K]^T + bias
// 128x128 CTA tile, BK=32, 8 warps as 2(m) x 4(n). 3-term correction.
// Output either fp32 (outf) or bf16 hi/lo (outh/outl).
// ---------------------------------------------------------------------------
struct GemmP {
    const __nv_bfloat16 *ahi, *alo, *whi, *wlo;
    const float* bias;
    float* outf;
    __nv_bfloat16 *outh, *outl;
};

#define GBK 32
#define GT_BYTES (128 * GBK * 2)   // 8192 B per tile

__global__ __launch_bounds__(256, 1) void gemm_hmma(GemmP p0, GemmP p1, GemmP p2)
{
    __shared__ char smem[4 * GT_BYTES];   // Ahi | Alo | Whi | Wlo

    GemmP p = (blockIdx.z == 0) ? p0 : (blockIdx.z == 1 ? p1 : p2);

    const int tid  = threadIdx.x;
    const int lane = tid & 31;
    const int wid  = tid >> 5;
    const int wm   = wid & 1;
    const int wn   = wid >> 1;
    const int bm   = blockIdx.y * 128;
    const int bn   = blockIdx.x * 128;

    const uint32_t sb  = smem_u32(smem);
    const uint32_t sAh = sb;
    const uint32_t sAl = sb + GT_BYTES;
    const uint32_t sWh = sb + 2 * GT_BYTES;
    const uint32_t sWl = sb + 3 * GT_BYTES;

    const int u  = tid & 3;
    const int r0 = tid >> 2;
    const int r1 = r0 + 64;
    const uint32_t d0 = (uint32_t)(r0 * 64 + ((u ^ ((r0 >> 1) & 3)) << 4));
    const uint32_t d1 = (uint32_t)(r1 * 64 + ((u ^ ((r1 >> 1) & 3)) << 4));
    const size_t offA0 = (size_t)(bm + r0) * DM + u * 8;
    const size_t offA1 = (size_t)(bm + r1) * DM + u * 8;
    const size_t offW0 = (size_t)(bn + r0) * DM + u * 8;
    const size_t offW1 = (size_t)(bn + r1) * DM + u * 8;

    const int sub = lane >> 3;
    const int a_r16  = ((sub & 1) << 3) + (lane & 7);
    const int a_usel = sub >> 1;
    const int b_nt   = sub >> 1;
    const int b_usel = sub & 1;
    const int b_r8   = lane & 7;

    int arow[4], asw[4];
    #pragma unroll
    for (int mt = 0; mt < 4; mt++) {
        const int gr = wm * 64 + mt * 16 + a_r16;
        arow[mt] = gr * 64;
        asw[mt]  = (gr >> 1) & 3;
    }
    int brow[2], bsw[2];
    #pragma unroll
    for (int j = 0; j < 2; j++) {
        const int nr = wn * 32 + (2 * j + b_nt) * 8 + b_r8;
        brow[j] = nr * 64;
        bsw[j]  = (nr >> 1) & 3;
    }

    float acc[4][4][4];
    #pragma unroll
    for (int mt = 0; mt < 4; mt++)
        #pragma unroll
        for (int nt = 0; nt < 4; nt++)
            #pragma unroll
            for (int r = 0; r < 4; r++) acc[mt][nt][r] = 0.f;

    uint4 fAh0, fAh1, fAl0, fAl1, fWh0, fWh1, fWl0, fWl1;
    fAh0 = *(const uint4*)(p.ahi + offA0); fAh1 = *(const uint4*)(p.ahi + offA1);
    fAl0 = *(const uint4*)(p.alo + offA0); fAl1 = *(const uint4*)(p.alo + offA1);
    fWh0 = *(const uint4*)(p.whi + offW0); fWh1 = *(const uint4*)(p.whi + offW1);
    fWl0 = *(const uint4*)(p.wlo + offW0); fWl1 = *(const uint4*)(p.wlo + offW1);

    const int NCH = DM / GBK;   // 32
    for (int ch = 0; ch < NCH; ch++) {
        __syncthreads();
        *(uint4*)(smem + (sAh - sb) + d0) = fAh0;
        *(uint4*)(smem + (sAh - sb) + d1) = fAh1;
        *(uint4*)(smem + (sAl - sb) + d0) = fAl0;
        *(uint4*)(smem + (sAl - sb) + d1) = fAl1;
        *(uint4*)(smem + (sWh - sb) + d0) = fWh0;
        *(uint4*)(smem + (sWh - sb) + d1) = fWh1;
        *(uint4*)(smem + (sWl - sb) + d0) = fWl0;
        *(uint4*)(smem + (sWl - sb) + d1) = fWl1;
        __syncthreads();

        if (ch + 1 < NCH) {
            const int kb = (ch + 1) * GBK;
            fAh0 = *(const uint4*)(p.ahi + offA0 + kb);
            fAh1 = *(const uint4*)(p.ahi + offA1 + kb);
            fAl0 = *(const uint4*)(p.alo + offA0 + kb);
            fAl1 = *(const uint4*)(p.alo + offA1 + kb);
            fWh0 = *(const uint4*)(p.whi + offW0 + kb);
            fWh1 = *(const uint4*)(p.whi + offW1 + kb);
            fWl0 = *(const uint4*)(p.wlo + offW0 + kb);
            fWl1 = *(const uint4*)(p.wlo + offW1 + kb);
        }

        #pragma unroll
        for (int ks = 0; ks < 2; ks++) {
            uint32_t bh[4][2], bl[4][2];
            #pragma unroll
            for (int j = 0; j < 2; j++) {
                const uint32_t uoff =
                    (uint32_t)(((2 * ks + b_usel) ^ bsw[j]) << 4) + brow[j];
                ldmx4(&bh[2 * j][0], sWh + uoff);
                ldmx4(&bl[2 * j][0], sWl + uoff);
            }
            #pragma unroll
            for (int mt = 0; mt < 4; mt++) {
                uint32_t ah[4], al[4];
                const uint32_t uoff =
                    (uint32_t)(((2 * ks + a_usel) ^ asw[mt]) << 4) + arow[mt];
                ldmx4(ah, sAh + uoff);
                ldmx4(al, sAl + uoff);
                #pragma unroll
                for (int nt = 0; nt < 4; nt++) {
                    mma_bf16(acc[mt][nt], ah, bh[nt]);
                    mma_bf16(acc[mt][nt], ah, bl[nt]);
                    mma_bf16(acc[mt][nt], al, bh[nt]);
                }
            }
        }
    }

    // ---- epilogue: bias add, then fp32 or bf16 hi/lo store
    #pragma unroll
    for (int mt = 0; mt < 4; mt++) {
        const int row0 = bm + wm * 64 + mt * 16 + (lane >> 2);
        #pragma unroll
        for (int nt = 0; nt < 4; nt++) {
            const int col = bn + wn * 32 + nt * 8 + (lane & 3) * 2;
            const float2 bv = *(const float2*)(p.bias + col);
            float x0 = acc[mt][nt][0] + bv.x;
            float y0 = acc[mt][nt][1] + bv.y;
            float x1 = acc[mt][nt][2] + bv.x;
            float y1 = acc[mt][nt][3] + bv.y;
            if (p.outf) {
                *(float2*)(p.outf + (size_t)row0 * DM + col)       = make_float2(x0, y0);
                *(float2*)(p.outf + (size_t)(row0 + 8) * DM + col) = make_float2(x1, y1);
            } else {
                uint32_t l0, l1;
                uint32_t h0 = split2(x0, y0, l0);
                uint32_t h1 = split2(x1, y1, l1);
                *(uint32_t*)(p.outh + (size_t)row0 * DM + col)       = h0;
                *(uint32_t*)(p.outl + (size_t)row0 * DM + col)       = l0;
                *(uint32_t*)(p.outh + (size_t)(row0 + 8) * DM + col) = h1;
                *(uint32_t*)(p.outl + (size_t)(row0 + 8) * DM + col) = l1;
            }
        }
    }
}

// ---------------------------------------------------------------------------
// Flash attention with HMMA (3-term bf16 error correction both GEMMs).
// CTA = 128 queries x one (b,h); 8 warps, warp = m16; KV block = 64.
// smem 64KB: Qh,Ql[128x64] Kh,Kl[64x64] Vh,Vl[64x64], 128B rows, u^(r&7) swizzle.
// ---------------------------------------------------------------------------
#define ATT_SMEM (64 * 1024)

__global__ __launch_bounds__(256, 2) void flash_attn_mma(
    const __nv_bfloat16* __restrict__ Qh, const __nv_bfloat16* __restrict__ Ql,
    const __nv_bfloat16* __restrict__ Kh, const __nv_bfloat16* __restrict__ Kl,
    const __nv_bfloat16* __restrict__ Vh, const __nv_bfloat16* __restrict__ Vl,
    const int* __restrict__ mask,
    __nv_bfloat16* __restrict__ Oh, __nv_bfloat16* __restrict__ Ol)
{
    extern __shared__ char sm[];
    const uint32_t sb  = smem_u32(sm);
    const uint32_t sQh = sb,          sQl = sb + 16384;
    const uint32_t sKh = sb + 32768,  sKl = sb + 40960;
    const uint32_t sVh = sb + 49152,  sVl = sb + 57344;

    const int tid  = threadIdx.x;
    const int lane = tid & 31;
    const int wid  = tid >> 5;
    const int qb   = blockIdx.x;
    const int bh   = blockIdx.y;
    const int b    = bh >> 4;
    const int h    = bh & 15;
    const int q0   = qb * 128;
    const int rowbase = b * S_LEN;
    const int hoff = h * DK;
    const int allones = g_mask_ones;

    // ---- load Q tile (128 x 64 hi/lo), swizzled
    #pragma unroll
    for (int t = 0; t < 4; t++) {
        const int idx = tid + t * 256;      // 0..1023
        const int r = idx >> 3, uu = idx & 7;
        const size_t g = (size_t)(rowbase + q0 + r) * DM + hoff + uu * 8;
        const uint32_t d = (uint32_t)(r * 128 + ((uu ^ (r & 7)) << 4));
        *(uint4*)(sm + (sQh - sb) + d) = *(const uint4*)(Qh + g);
        *(uint4*)(sm + (sQl - sb) + d) = *(const uint4*)(Ql + g);
    }

    // lane geometry
    const int sub = lane >> 3, l7 = lane & 7;
    const int a_r  = ((sub & 1) << 3) + l7;    // A row-in-tile
    const int a_us = sub >> 1;                 // A k-unit select
    const int b_nt = sub >> 1, b_us = sub & 1; // B (K) geometry
    const int qrow = wid * 16 + a_r;           // Q smem row for this lane
    const int vro  = ((sub & 1) << 3) + l7;    // V token row-in-ktile
    const int vus  = sub >> 1;                 // V unit select

    float o[8][4];
    #pragma unroll
    for (int nt = 0; nt < 8; nt++)
        #pragma unroll
        for (int e = 0; e < 4; e++) o[nt][e] = 0.f;
    float m0 = -3.0e38f, m1 = -3.0e38f, l0 = 0.f, l1 = 0.f;

    for (int kb = 0; kb < S_LEN / 64; kb++) {
        const int k0g = kb * 64;

        // ---- load K/V tiles (64 x 64 hi/lo each)
        #pragma unroll
        for (int t = 0; t < 2; t++) {
            const int idx = tid + t * 256;   // 0..511
            const int r = idx >> 3, uu = idx & 7;
            const size_t g = (size_t)(rowbase + k0g + r) * DM + hoff + uu * 8;
            const uint32_t d = (uint32_t)(r * 128 + ((uu ^ (r & 7)) << 4));
            *(uint4*)(sm + (sKh - sb) + d) = *(const uint4*)(Kh + g);
            *(uint4*)(sm + (sKl - sb) + d) = *(const uint4*)(Kl + g);
            *(uint4*)(sm + (sVh - sb) + d) = *(const uint4*)(Vh + g);
            *(uint4*)(sm + (sVl - sb) + d) = *(const uint4*)(Vl + g);
        }
        __syncthreads();

        // ---- S = Q K^T (3-term)
        float c[8][4];
        #pragma unroll
        for (int j = 0; j < 8; j++)
            #pragma unroll
            for (int e = 0; e < 4; e++) c[j][e] = 0.f;

        #pragma unroll
        for (int ks = 0; ks < 4; ks++) {
            uint32_t ah[4], al[4];
            const uint32_t ua = (uint32_t)((((2 * ks + a_us) ^ (qrow & 7)) << 4) + qrow * 128);
            ldmx4(ah, sQh + ua);
            ldmx4(al, sQl + ua);
            #pragma unroll
            for (int jp = 0; jp < 4; jp++) {
                uint32_t bhf[4], blf[4];
                const int nr = jp * 16 + b_nt * 8 + l7;
                const uint32_t ub = (uint32_t)((((2 * ks + b_us) ^ (nr & 7)) << 4) + nr * 128);
                ldmx4(bhf, sKh + ub);
                ldmx4(blf, sKl + ub);
                mma_bf16(c[2 * jp],     ah, bhf);
                mma_bf16(c[2 * jp],     ah, blf);
                mma_bf16(c[2 * jp],     al, bhf);
                mma_bf16(c[2 * jp + 1], ah, bhf + 2);
                mma_bf16(c[2 * jp + 1], ah, blf + 2);
                mma_bf16(c[2 * jp + 1], al, bhf + 2);
            }
        }

        // ---- scale + mask
        if (allones) {
            #pragma unroll
            for (int j = 0; j < 8; j++)
                #pragma unroll
                for (int e = 0; e < 4; e++) c[j][e] *= 0.125f;
        } else {
            const int qg0 = q0 + wid * 16 + (lane >> 2);
            #pragma unroll
            for (int j = 0; j < 8; j++) {
                const int colb = k0g + j * 8 + 2 * (lane & 3);
                #pragma unroll
                for (int e = 0; e < 4; e++) {
                    const int qq = (e < 2) ? qg0 : qg0 + 8;
                    const int kk = colb + (e & 1);
                    const int mv = mask[(size_t)qq * S_LEN + kk];
                    c[j][e] = mv ? c[j][e] * 0.125f : -1e9f;
                }
            }
        }

        // ---- online softmax update
        float rm0 = -3.0e38f, rm1 = -3.0e38f;
        #pragma unroll
        for (int j = 0; j < 8; j++) {
            rm0 = fmaxf(rm0, fmaxf(c[j][0], c[j][1]));
            rm1 = fmaxf(rm1, fmaxf(c[j][2], c[j][3]));
        }
        rm0 = fmaxf(rm0, __shfl_xor_sync(0xffffffffu, rm0, 1));
        rm0 = fmaxf(rm0, __shfl_xor_sync(0xffffffffu, rm0, 2));
        rm1 = fmaxf(rm1, __shfl_xor_sync(0xffffffffu, rm1, 1));
        rm1 = fmaxf(rm1, __shfl_xor_sync(0xffffffffu, rm1, 2));
        const float mn0 = fmaxf(m0, rm0), mn1 = fmaxf(m1, rm1);
        const float al0 = __expf(m0 - mn0), al1 = __expf(m1 - mn1);
        float rs0 = 0.f, rs1 = 0.f;
        #pragma unroll
        for (int j = 0; j < 8; j++) {
            c[j][0] = __expf(c[j][0] - mn0);
            c[j][1] = __expf(c[j][1] - mn0);
            c[j][2] = __expf(c[j][2] - mn1);
            c[j][3] = __expf(c[j][3] - mn1);
            rs0 += c[j][0] + c[j][1];
            rs1 += c[j][2] + c[j][3];
        }
        rs0 += __shfl_xor_sync(0xffffffffu, rs0, 1);
        rs0 += __shfl_xor_sync(0xffffffffu, rs0, 2);
        rs1 += __shfl_xor_sync(0xffffffffu, rs1, 1);
        rs1 += __shfl_xor_sync(0xffffffffu, rs1, 2);
        l0 = l0 * al0 + rs0;
        l1 = l1 * al1 + rs1;
        m0 = mn0; m1 = mn1;
        #pragma unroll
        for (int nt = 0; nt < 8; nt++) {
            o[nt][0] *= al0; o[nt][1] *= al0;
            o[nt][2] *= al1; o[nt][3] *= al1;
        }

        // ---- O += P V (3-term); P packed register-locally from c
        #pragma unroll
        for (int kt = 0; kt < 4; kt++) {
            uint32_t ph[4], pl[4];
            ph[0] = split2(c[2 * kt][0],     c[2 * kt][1],     pl[0]);
            ph[1] = split2(c[2 * kt][2],     c[2 * kt][3],     pl[1]);
            ph[2] = split2(c[2 * kt + 1][0], c[2 * kt + 1][1], pl[2]);
            ph[3] = split2(c[2 * kt + 1][2], c[2 * kt + 1][3], pl[3]);

            const int tv = kt * 16 + vro;
            #pragma unroll
            for (int dp = 0; dp < 4; dp++) {
                uint32_t vh4[4], vl4[4];
                const uint32_t uv = (uint32_t)((((2 * dp + vus) ^ (tv & 7)) << 4) + tv * 128);
                ldmx4t(vh4, sVh + uv);
                ldmx4t(vl4, sVl + uv);
                mma_bf16(o[2 * dp],     ph, vh4);
                mma_bf16(o[2 * dp],     ph, vl4);
                mma_bf16(o[2 * dp],     pl, vh4);
                mma_bf16(o[2 * dp + 1], ph, vh4 + 2);
                mma_bf16(o[2 * dp + 1], ph, vl4 + 2);
                mma_bf16(o[2 * dp + 1], pl, vh4 + 2);
            }
        }
        __syncthreads();
    }

    // ---- epilogue: O / l -> bf16 hi/lo
    const float inv0 = 1.f / l0, inv1 = 1.f / l1;
    const int gr0 = rowbase + q0 + wid * 16 + (lane >> 2);
    #pragma unroll
    for (int nt = 0; nt < 8; nt++) {
        const int col = hoff + nt * 8 + 2 * (lane & 3);
        uint32_t lo0, lo1;
        const uint32_t h0 = split2(o[nt][0] * inv0, o[nt][1] * inv0, lo0);
        const uint32_t h1 = split2(o[nt][2] * inv1, o[nt][3] * inv1, lo1);
        *(uint32_t*)(Oh + (size_t)gr0 * DM + col)       = h0;
        *(uint32_t*)(Ol + (size_t)gr0 * DM + col)       = lo0;
        *(uint32_t*)(Oh + (size_t)(gr0 + 8) * DM + col) = h1;
        *(uint32_t*)(Ol + (size_t)(gr0 + 8) * DM + col) = lo1;
    }
}

// ---------------------------------------------------------------------------
extern "C" void kernel_launch(void* const* d_in, const int* in_sizes, int n_in,
                              void* d_out, int out_size)
{
    const float* q    = (const float*)d_in[0];
    const float* k    = (const float*)d_in[1];
    const float* v    = (const float*)d_in[2];
    const int*   mask = (const int*)  d_in[3];
    const float* Wq   = (const float*)d_in[4];
    const float* bq   = (const float*)d_in[5];
    const float* Wk   = (const float*)d_in[6];
    const float* bk   = (const float*)d_in[7];
    const float* Wv   = (const float*)d_in[8];
    const float* bv   = (const float*)d_in[9];
    const float* Wo   = (const float*)d_in[10];
    const float* bo   = (const float*)d_in[11];
    float* out = (float*)d_out;

    __nv_bfloat16 *qh, *ql, *kh, *kl, *vh, *vl;
    __nv_bfloat16 *wqh, *wql, *wkh, *wkl, *wvh, *wvl, *woh, *wol;
    __nv_bfloat16 *Qph, *Qpl, *Kph, *Kpl, *Vph, *Vpl, *AOh, *AOl;
    cudaGetSymbolAddress((void**)&qh,  g_q_hi);  cudaGetSymbolAddress((void**)&ql,  g_q_lo);
    cudaGetSymbolAddress((void**)&kh,  g_k_hi);  cudaGetSymbolAddress((void**)&kl,  g_k_lo);
    cudaGetSymbolAddress((void**)&vh,  g_v_hi);  cudaGetSymbolAddress((void**)&vl,  g_v_lo);
    cudaGetSymbolAddress((void**)&wqh, g_Wq_hi); cudaGetSymbolAddress((void**)&wql, g_Wq_lo);
    cudaGetSymbolAddress((void**)&wkh, g_Wk_hi); cudaGetSymbolAddress((void**)&wkl, g_Wk_lo);
    cudaGetSymbolAddress((void**)&wvh, g_Wv_hi); cudaGetSymbolAddress((void**)&wvl, g_Wv_lo);
    cudaGetSymbolAddress((void**)&woh, g_Wo_hi); cudaGetSymbolAddress((void**)&wol, g_Wo_lo);
    cudaGetSymbolAddress((void**)&Qph, g_Qph);   cudaGetSymbolAddress((void**)&Qpl, g_Qpl);
    cudaGetSymbolAddress((void**)&Kph, g_Kph);   cudaGetSymbolAddress((void**)&Kpl, g_Kpl);
    cudaGetSymbolAddress((void**)&Vph, g_Vph);   cudaGetSymbolAddress((void**)&Vpl, g_Vpl);
    cudaGetSymbolAddress((void**)&AOh, g_AOh);   cudaGetSymbolAddress((void**)&AOl, g_AOl);

    cudaFuncSetAttribute(flash_attn_mma, cudaFuncAttributeMaxDynamicSharedMemorySize,
                         ATT_SMEM);

    const int n4_in = MROWS * DM / 4;
    const int n4_w  = DM * DM / 4;

    // mask all-ones check
    reset_flag<<<1, 1>>>();
    check_mask<<<1024, 256>>>(mask, S_LEN * S_LEN);

    // split inputs + weights to bf16 hi/lo
    split_bf16<<<n4_in / 256, 256>>>(q,  qh,  ql,  n4_in);
    split_bf16<<<n4_in / 256, 256>>>(k,  kh,  kl,  n4_in);
    split_bf16<<<n4_in / 256, 256>>>(v,  vh,  vl,  n4_in);
    split_bf16<<<n4_w  / 256, 256>>>(Wq, wqh, wql, n4_w);
    split_bf16<<<n4_w  / 256, 256>>>(Wk, wkh, wkl, n4_w);
    split_bf16<<<n4_w  / 256, 256>>>(Wv, wvh, wvl, n4_w);
    split_bf16<<<n4_w  / 256, 256>>>(Wo, woh, wol, n4_w);

    // fused Q/K/V projections -> bf16 hi/lo outputs
    GemmP pq = { qh, ql, wqh, wql, bq, nullptr, Qph, Qpl };
    GemmP pk = { kh, kl, wkh, wkl, bk, nullptr, Kph, Kpl };
    GemmP pv = { vh, vl, wvh, wvl, bv, nullptr, Vph, Vpl };
    dim3 gg3(DM / 128, MROWS / 128, 3);
    gemm_hmma<<<gg3, 256>>>(pq, pk, pv);

    // attention (HMMA) -> AO hi/lo
    dim3 ga(S_LEN / 128, B_SZ * NH);   // (16, 32)
    flash_attn_mma<<<ga, 256, ATT_SMEM>>>(Qph, Qpl, Kph, Kpl, Vph, Vpl, mask,
                                          AOh, AOl);

    // final projection -> fp32 out
    GemmP po = { AOh, AOl, woh, wol, bo, out, nullptr, nullptr };
    dim3 gg1(DM / 128, MROWS / 128, 1);
    gemm_hmma<<<gg1, 256>>>(po, po, po);
}

// round 7
// speedup vs baseline: 2.9036x; 1.0002x over previous
#include <cuda_runtime.h>
#include <cuda_bf16.h>
#include <cstdint>
#include <math.h>

#define S_LEN 2048
#define B_SZ  2
#define DM    1024
#define NH    16
#define DK    64
#define MROWS (B_SZ * S_LEN)   // 4096

// ---------------------------------------------------------------------------
// Scratch (static device memory; no allocations allowed)
// ---------------------------------------------------------------------------
// input splits
__device__ __nv_bfloat16 g_q_hi[MROWS * DM], g_q_lo[MROWS * DM];
__device__ __nv_bfloat16 g_k_hi[MROWS * DM], g_k_lo[MROWS * DM];
__device__ __nv_bfloat16 g_v_hi[MROWS * DM], g_v_lo[MROWS * DM];
__device__ __nv_bfloat16 g_Wq_hi[DM * DM], g_Wq_lo[DM * DM];
__device__ __nv_bfloat16 g_Wk_hi[DM * DM], g_Wk_lo[DM * DM];
__device__ __nv_bfloat16 g_Wv_hi[DM * DM], g_Wv_lo[DM * DM];
__device__ __nv_bfloat16 g_Wo_hi[DM * DM], g_Wo_lo[DM * DM];
// projected Q/K/V (hi/lo) and attention output (hi/lo)
__device__ __nv_bfloat16 g_Qph[MROWS * DM], g_Qpl[MROWS * DM];
__device__ __nv_bfloat16 g_Kph[MROWS * DM], g_Kpl[MROWS * DM];
__device__ __nv_bfloat16 g_Vph[MROWS * DM], g_Vpl[MROWS * DM];
__device__ __nv_bfloat16 g_AOh[MROWS * DM], g_AOl[MROWS * DM];
// mask all-ones flag
__device__ int g_mask_ones;

// ---------------------------------------------------------------------------
// HMMA helpers (base sm_100 target: mma.sync + ldmatrix)
// ---------------------------------------------------------------------------
__device__ __forceinline__ uint32_t smem_u32(const void* p) {
    uint32_t a;
    asm("{ .reg .u64 t; cvta.to.shared.u64 t, %1; cvt.u32.u64 %0, t; }"
        : "=r"(a) : "l"(p));
    return a;
}

__device__ __forceinline__ void ldmx4(uint32_t* r, uint32_t addr) {
    asm volatile("ldmatrix.sync.aligned.m8n8.x4.shared.b16 {%0,%1,%2,%3}, [%4];"
                 : "=r"(r[0]), "=r"(r[1]), "=r"(r[2]), "=r"(r[3]) : "r"(addr));
}

__device__ __forceinline__ void ldmx4t(uint32_t* r, uint32_t addr) {
    asm volatile("ldmatrix.sync.aligned.m8n8.x4.trans.shared.b16 {%0,%1,%2,%3}, [%4];"
                 : "=r"(r[0]), "=r"(r[1]), "=r"(r[2]), "=r"(r[3]) : "r"(addr));
}

__device__ __forceinline__ void mma_bf16(float* c, const uint32_t* a,
                                         const uint32_t* b) {
    asm volatile(
        "mma.sync.aligned.m16n8k16.row.col.f32.bf16.bf16.f32 "
        "{%0,%1,%2,%3}, {%4,%5,%6,%7}, {%8,%9}, {%0,%1,%2,%3};"
        : "+f"(c[0]), "+f"(c[1]), "+f"(c[2]), "+f"(c[3])
        : "r"(a[0]), "r"(a[1]), "r"(a[2]), "r"(a[3]), "r"(b[0]), "r"(b[1]));
}

// pack (x,y) -> bf16x2 hi bits; residual -> bf16x2 lo bits
__device__ __forceinline__ uint32_t split2(float x, float y, uint32_t& lo) {
    __nv_bfloat16 hx = __float2bfloat16(x), hy = __float2bfloat16(y);
    __nv_bfloat16 lx = __float2bfloat16(x - __bfloat162float(hx));
    __nv_bfloat16 ly = __float2bfloat16(y - __bfloat162float(hy));
    __nv_bfloat162 h(hx, hy), l(lx, ly);
    lo = *reinterpret_cast<uint32_t*>(&l);
    return *reinterpret_cast<uint32_t*>(&h);
}

// ---------------------------------------------------------------------------
// Mask all-ones detection
// ---------------------------------------------------------------------------
__global__ void reset_flag() { g_mask_ones = 1; }

__global__ __launch_bounds__(256) void check_mask(const int* __restrict__ m, int n) {
    int i = blockIdx.x * blockDim.x + threadIdx.x;
    int ok = 1;
    for (; i < n; i += gridDim.x * blockDim.x) ok &= (m[i] != 0);
    ok = __all_sync(0xffffffffu, ok);
    if ((threadIdx.x & 31) == 0 && !ok) atomicExch(&g_mask_ones, 0);
}

// ---------------------------------------------------------------------------
// Split fp32 -> (bf16 hi, bf16 lo)
// ---------------------------------------------------------------------------
__global__ __launch_bounds__(256) void split_bf16(
    const float* __restrict__ x, __nv_bfloat16* __restrict__ hi,
    __nv_bfloat16* __restrict__ lo, int n4)
{
    int i = blockIdx.x * blockDim.x + threadIdx.x;
    if (i >= n4) return;
    float4 v = ((const float4*)x)[i];
    uint32_t l0, l1, h0, h1;
    h0 = split2(v.x, v.y, l0);
    h1 = split2(v.z, v.w, l1);
    uint32_t* hp = (uint32_t*)hi;
    uint32_t* lp = (uint32_t*)lo;
    hp[2 * i] = h0; hp[2 * i + 1] = h1;
    lp[2 * i] = l0; lp[2 * i + 1] = l1;
}

// ---------------------------------------------------------------------------
// HMMA GEMM:  C[M,N] = (Ahi+Alo)[M,K] @ (Whi+Wlo)[N,K]^T + bias
// 128x128 CTA tile, BK=32, 8 warps as 2(m) x 4(n). 3-term correction.
// Output either fp32 (outf) or bf16 hi/lo (outh/outl).
// ---------------------------------------------------------------------------
struct GemmP {
    const __nv_bfloat16 *ahi, *alo, *whi, *wlo;
    const float* bias;
    float* outf;
    __nv_bfloat16 *outh, *outl;
};

#define GBK 32
#define GT_BYTES (128 * GBK * 2)   // 8192 B per tile

__global__ __launch_bounds__(256, 1) void gemm_hmma(GemmP p0, GemmP p1, GemmP p2)
{
    __shared__ char smem[4 * GT_BYTES];   // Ahi | Alo | Whi | Wlo

    GemmP p = (blockIdx.z == 0) ? p0 : (blockIdx.z == 1 ? p1 : p2);

    const int tid  = threadIdx.x;
    const int lane = tid & 31;
    const int wid  = tid >> 5;
    const int wm   = wid & 1;
    const int wn   = wid >> 1;
    const int bm   = blockIdx.y * 128;
    const int bn   = blockIdx.x * 128;

    const uint32_t sb  = smem_u32(smem);
    const uint32_t sAh = sb;
    const uint32_t sAl = sb + GT_BYTES;
    const uint32_t sWh = sb + 2 * GT_BYTES;
    const uint32_t sWl = sb + 3 * GT_BYTES;

    const int u  = tid & 3;
    const int r0 = tid >> 2;
    const int r1 = r0 + 64;
    const uint32_t d0 = (uint32_t)(r0 * 64 + ((u ^ ((r0 >> 1) & 3)) << 4));
    const uint32_t d1 = (uint32_t)(r1 * 64 + ((u ^ ((r1 >> 1) & 3)) << 4));
    const size_t offA0 = (size_t)(bm + r0) * DM + u * 8;
    const size_t offA1 = (size_t)(bm + r1) * DM + u * 8;
    const size_t offW0 = (size_t)(bn + r0) * DM + u * 8;
    const size_t offW1 = (size_t)(bn + r1) * DM + u * 8;

    const int sub = lane >> 3;
    const int a_r16  = ((sub & 1) << 3) + (lane & 7);
    const int a_usel = sub >> 1;
    const int b_nt   = sub >> 1;
    const int b_usel = sub & 1;
    const int b_r8   = lane & 7;

    int arow[4], asw[4];
    #pragma unroll
    for (int mt = 0; mt < 4; mt++) {
        const int gr = wm * 64 + mt * 16 + a_r16;
        arow[mt] = gr * 64;
        asw[mt]  = (gr >> 1) & 3;
    }
    int brow[2], bsw[2];
    #pragma unroll
    for (int j = 0; j < 2; j++) {
        const int nr = wn * 32 + (2 * j + b_nt) * 8 + b_r8;
        brow[j] = nr * 64;
        bsw[j]  = (nr >> 1) & 3;
    }

    float acc[4][4][4];
    #pragma unroll
    for (int mt = 0; mt < 4; mt++)
        #pragma unroll
        for (int nt = 0; nt < 4; nt++)
            #pragma unroll
            for (int r = 0; r < 4; r++) acc[mt][nt][r] = 0.f;

    uint4 fAh0, fAh1, fAl0, fAl1, fWh0, fWh1, fWl0, fWl1;
    fAh0 = *(const uint4*)(p.ahi + offA0); fAh1 = *(const uint4*)(p.ahi + offA1);
    fAl0 = *(const uint4*)(p.alo + offA0); fAl1 = *(const uint4*)(p.alo + offA1);
    fWh0 = *(const uint4*)(p.whi + offW0); fWh1 = *(const uint4*)(p.whi + offW1);
    fWl0 = *(const uint4*)(p.wlo + offW0); fWl1 = *(const uint4*)(p.wlo + offW1);

    const int NCH = DM / GBK;   // 32
    for (int ch = 0; ch < NCH; ch++) {
        __syncthreads();
        *(uint4*)(smem + (sAh - sb) + d0) = fAh0;
        *(uint4*)(smem + (sAh - sb) + d1) = fAh1;
        *(uint4*)(smem + (sAl - sb) + d0) = fAl0;
        *(uint4*)(smem + (sAl - sb) + d1) = fAl1;
        *(uint4*)(smem + (sWh - sb) + d0) = fWh0;
        *(uint4*)(smem + (sWh - sb) + d1) = fWh1;
        *(uint4*)(smem + (sWl - sb) + d0) = fWl0;
        *(uint4*)(smem + (sWl - sb) + d1) = fWl1;
        __syncthreads();

        if (ch + 1 < NCH) {
            const int kb = (ch + 1) * GBK;
            fAh0 = *(const uint4*)(p.ahi + offA0 + kb);
            fAh1 = *(const uint4*)(p.ahi + offA1 + kb);
            fAl0 = *(const uint4*)(p.alo + offA0 + kb);
            fAl1 = *(const uint4*)(p.alo + offA1 + kb);
            fWh0 = *(const uint4*)(p.whi + offW0 + kb);
            fWh1 = *(const uint4*)(p.whi + offW1 + kb);
            fWl0 = *(const uint4*)(p.wlo + offW0 + kb);
            fWl1 = *(const uint4*)(p.wlo + offW1 + kb);
        }

        #pragma unroll
        for (int ks = 0; ks < 2; ks++) {
            uint32_t bh[4][2], bl[4][2];
            #pragma unroll
            for (int j = 0; j < 2; j++) {
                const uint32_t uoff =
                    (uint32_t)(((2 * ks + b_usel) ^ bsw[j]) << 4) + brow[j];
                ldmx4(&bh[2 * j][0], sWh + uoff);
                ldmx4(&bl[2 * j][0], sWl + uoff);
            }
            #pragma unroll
            for (int mt = 0; mt < 4; mt++) {
                uint32_t ah[4], al[4];
                const uint32_t uoff =
                    (uint32_t)(((2 * ks + a_usel) ^ asw[mt]) << 4) + arow[mt];
                ldmx4(ah, sAh + uoff);
                ldmx4(al, sAl + uoff);
                #pragma unroll
                for (int nt = 0; nt < 4; nt++) {
                    mma_bf16(acc[mt][nt], ah, bh[nt]);
                    mma_bf16(acc[mt][nt], ah, bl[nt]);
                    mma_bf16(acc[mt][nt], al, bh[nt]);
                }
            }
        }
    }

    // ---- epilogue: bias add, then fp32 or bf16 hi/lo store
    #pragma unroll
    for (int mt = 0; mt < 4; mt++) {
        const int row0 = bm + wm * 64 + mt * 16 + (lane >> 2);
        #pragma unroll
        for (int nt = 0; nt < 4; nt++) {
            const int col = bn + wn * 32 + nt * 8 + (lane & 3) * 2;
            const float2 bv = *(const float2*)(p.bias + col);
            float x0 = acc[mt][nt][0] + bv.x;
            float y0 = acc[mt][nt][1] + bv.y;
            float x1 = acc[mt][nt][2] + bv.x;
            float y1 = acc[mt][nt][3] + bv.y;
            if (p.outf) {
                *(float2*)(p.outf + (size_t)row0 * DM + col)       = make_float2(x0, y0);
                *(float2*)(p.outf + (size_t)(row0 + 8) * DM + col) = make_float2(x1, y1);
            } else {
                uint32_t l0, l1;
                uint32_t h0 = split2(x0, y0, l0);
                uint32_t h1 = split2(x1, y1, l1);
                *(uint32_t*)(p.outh + (size_t)row0 * DM + col)       = h0;
                *(uint32_t*)(p.outl + (size_t)row0 * DM + col)       = l0;
                *(uint32_t*)(p.outh + (size_t)(row0 + 8) * DM + col) = h1;
                *(uint32_t*)(p.outl + (size_t)(row0 + 8) * DM + col) = l1;
            }
        }
    }
}

// ---------------------------------------------------------------------------
// Flash attention with HMMA (3-term bf16 error correction both GEMMs).
// CTA = 128 queries x one (b,h); 8 warps, warp = m16; KV block = 64.
// smem 64KB: Qh,Ql[128x64] Kh,Kl[64x64] Vh,Vl[64x64], 128B rows, u^(r&7) swizzle.
// ---------------------------------------------------------------------------
#define ATT_SMEM (64 * 1024)

__global__ __launch_bounds__(256, 2) void flash_attn_mma(
    const __nv_bfloat16* __restrict__ Qh, const __nv_bfloat16* __restrict__ Ql,
    const __nv_bfloat16* __restrict__ Kh, const __nv_bfloat16* __restrict__ Kl,
    const __nv_bfloat16* __restrict__ Vh, const __nv_bfloat16* __restrict__ Vl,
    const int* __restrict__ mask,
    __nv_bfloat16* __restrict__ Oh, __nv_bfloat16* __restrict__ Ol)
{
    extern __shared__ char sm[];
    const uint32_t sb  = smem_u32(sm);
    const uint32_t sQh = sb,          sQl = sb + 16384;
    const uint32_t sKh = sb + 32768,  sKl = sb + 40960;
    const uint32_t sVh = sb + 49152,  sVl = sb + 57344;

    const int tid  = threadIdx.x;
    const int lane = tid & 31;
    const int wid  = tid >> 5;
    const int qb   = blockIdx.x;
    const int bh   = blockIdx.y;
    const int b    = bh >> 4;
    const int h    = bh & 15;
    const int q0   = qb * 128;
    const int rowbase = b * S_LEN;
    const int hoff = h * DK;
    const int allones = g_mask_ones;

    // ---- load Q tile (128 x 64 hi/lo), swizzled
    #pragma unroll
    for (int t = 0; t < 4; t++) {
        const int idx = tid + t * 256;      // 0..1023
        const int r = idx >> 3, uu = idx & 7;
        const size_t g = (size_t)(rowbase + q0 + r) * DM + hoff + uu * 8;
        const uint32_t d = (uint32_t)(r * 128 + ((uu ^ (r & 7)) << 4));
        *(uint4*)(sm + (sQh - sb) + d) = *(const uint4*)(Qh + g);
        *(uint4*)(sm + (sQl - sb) + d) = *(const uint4*)(Ql + g);
    }

    // lane geometry
    const int sub = lane >> 3, l7 = lane & 7;
    const int a_r  = ((sub & 1) << 3) + l7;    // A row-in-tile
    const int a_us = sub >> 1;                 // A k-unit select
    const int b_nt = sub >> 1, b_us = sub & 1; // B (K) geometry
    const int qrow = wid * 16 + a_r;           // Q smem row for this lane
    const int vro  = ((sub & 1) << 3) + l7;    // V token row-in-ktile
    const int vus  = sub >> 1;                 // V unit select

    float o[8][4];
    #pragma unroll
    for (int nt = 0; nt < 8; nt++)
        #pragma unroll
        for (int e = 0; e < 4; e++) o[nt][e] = 0.f;
    float m0 = -3.0e38f, m1 = -3.0e38f, l0 = 0.f, l1 = 0.f;

    for (int kb = 0; kb < S_LEN / 64; kb++) {
        const int k0g = kb * 64;

        // ---- load K/V tiles (64 x 64 hi/lo each)
        #pragma unroll
        for (int t = 0; t < 2; t++) {
            const int idx = tid + t * 256;   // 0..511
            const int r = idx >> 3, uu = idx & 7;
            const size_t g = (size_t)(rowbase + k0g + r) * DM + hoff + uu * 8;
            const uint32_t d = (uint32_t)(r * 128 + ((uu ^ (r & 7)) << 4));
            *(uint4*)(sm + (sKh - sb) + d) = *(const uint4*)(Kh + g);
            *(uint4*)(sm + (sKl - sb) + d) = *(const uint4*)(Kl + g);
            *(uint4*)(sm + (sVh - sb) + d) = *(const uint4*)(Vh + g);
            *(uint4*)(sm + (sVl - sb) + d) = *(const uint4*)(Vl + g);
        }
        __syncthreads();

        // ---- S = Q K^T (3-term)
        float c[8][4];
        #pragma unroll
        for (int j = 0; j < 8; j++)
            #pragma unroll
            for (int e = 0; e < 4; e++) c[j][e] = 0.f;

        #pragma unroll
        for (int ks = 0; ks < 4; ks++) {
            uint32_t ah[4], al[4];
            const uint32_t ua = (uint32_t)((((2 * ks + a_us) ^ (qrow & 7)) << 4) + qrow * 128);
            ldmx4(ah, sQh + ua);
            ldmx4(al, sQl + ua);
            #pragma unroll
            for (int jp = 0; jp < 4; jp++) {
                uint32_t bhf[4], blf[4];
                const int nr = jp * 16 + b_nt * 8 + l7;
                const uint32_t ub = (uint32_t)((((2 * ks + b_us) ^ (nr & 7)) << 4) + nr * 128);
                ldmx4(bhf, sKh + ub);
                ldmx4(blf, sKl + ub);
                mma_bf16(c[2 * jp],     ah, bhf);
                mma_bf16(c[2 * jp],     ah, blf);
                mma_bf16(c[2 * jp],     al, bhf);
                mma_bf16(c[2 * jp + 1], ah, bhf + 2);
                mma_bf16(c[2 * jp + 1], ah, blf + 2);
                mma_bf16(c[2 * jp + 1], al, bhf + 2);
            }
        }

        // ---- scale + mask
        if (allones) {
            #pragma unroll
            for (int j = 0; j < 8; j++)
                #pragma unroll
                for (int e = 0; e < 4; e++) c[j][e] *= 0.125f;
        } else {
            const int qg0 = q0 + wid * 16 + (lane >> 2);
            #pragma unroll
            for (int j = 0; j < 8; j++) {
                const int colb = k0g + j * 8 + 2 * (lane & 3);
                #pragma unroll
                for (int e = 0; e < 4; e++) {
                    const int qq = (e < 2) ? qg0 : qg0 + 8;
                    const int kk = colb + (e & 1);
                    const int mv = mask[(size_t)qq * S_LEN + kk];
                    c[j][e] = mv ? c[j][e] * 0.125f : -1e9f;
                }
            }
        }

        // ---- online softmax update
        float rm0 = -3.0e38f, rm1 = -3.0e38f;
        #pragma unroll
        for (int j = 0; j < 8; j++) {
            rm0 = fmaxf(rm0, fmaxf(c[j][0], c[j][1]));
            rm1 = fmaxf(rm1, fmaxf(c[j][2], c[j][3]));
        }
        rm0 = fmaxf(rm0, __shfl_xor_sync(0xffffffffu, rm0, 1));
        rm0 = fmaxf(rm0, __shfl_xor_sync(0xffffffffu, rm0, 2));
        rm1 = fmaxf(rm1, __shfl_xor_sync(0xffffffffu, rm1, 1));
        rm1 = fmaxf(rm1, __shfl_xor_sync(0xffffffffu, rm1, 2));
        const float mn0 = fmaxf(m0, rm0), mn1 = fmaxf(m1, rm1);
        const float al0 = __expf(m0 - mn0), al1 = __expf(m1 - mn1);
        float rs0 = 0.f, rs1 = 0.f;
        #pragma unroll
        for (int j = 0; j < 8; j++) {
            c[j][0] = __expf(c[j][0] - mn0);
            c[j][1] = __expf(c[j][1] - mn0);
            c[j][2] = __expf(c[j][2] - mn1);
            c[j][3] = __expf(c[j][3] - mn1);
            rs0 += c[j][0] + c[j][1];
            rs1 += c[j][2] + c[j][3];
        }
        rs0 += __shfl_xor_sync(0xffffffffu, rs0, 1);
        rs0 += __shfl_xor_sync(0xffffffffu, rs0, 2);
        rs1 += __shfl_xor_sync(0xffffffffu, rs1, 1);
        rs1 += __shfl_xor_sync(0xffffffffu, rs1, 2);
        l0 = l0 * al0 + rs0;
        l1 = l1 * al1 + rs1;
        m0 = mn0; m1 = mn1;
        #pragma unroll
        for (int nt = 0; nt < 8; nt++) {
            o[nt][0] *= al0; o[nt][1] *= al0;
            o[nt][2] *= al1; o[nt][3] *= al1;
        }

        // ---- O += P V (3-term); P packed register-locally from c
        #pragma unroll
        for (int kt = 0; kt < 4; kt++) {
            uint32_t ph[4], pl[4];
            ph[0] = split2(c[2 * kt][0],     c[2 * kt][1],     pl[0]);
            ph[1] = split2(c[2 * kt][2],     c[2 * kt][3],     pl[1]);
            ph[2] = split2(c[2 * kt + 1][0], c[2 * kt + 1][1], pl[2]);
            ph[3] = split2(c[2 * kt + 1][2], c[2 * kt + 1][3], pl[3]);

            const int tv = kt * 16 + vro;
            #pragma unroll
            for (int dp = 0; dp < 4; dp++) {
                uint32_t vh4[4], vl4[4];
                const uint32_t uv = (uint32_t)((((2 * dp + vus) ^ (tv & 7)) << 4) + tv * 128);
                ldmx4t(vh4, sVh + uv);
                ldmx4t(vl4, sVl + uv);
                mma_bf16(o[2 * dp],     ph, vh4);
                mma_bf16(o[2 * dp],     ph, vl4);
                mma_bf16(o[2 * dp],     pl, vh4);
                mma_bf16(o[2 * dp + 1], ph, vh4 + 2);
                mma_bf16(o[2 * dp + 1], ph, vl4 + 2);
                mma_bf16(o[2 * dp + 1], pl, vh4 + 2);
            }
        }
        __syncthreads();
    }

    // ---- epilogue: O / l -> bf16 hi/lo
    const float inv0 = 1.f / l0, inv1 = 1.f / l1;
    const int gr0 = rowbase + q0 + wid * 16 + (lane >> 2);
    #pragma unroll
    for (int nt = 0; nt < 8; nt++) {
        const int col = hoff + nt * 8 + 2 * (lane & 3);
        uint32_t lo0, lo1;
        const uint32_t h0 = split2(o[nt][0] * inv0, o[nt][1] * inv0, lo0);
        const uint32_t h1 = split2(o[nt][2] * inv1, o[nt][3] * inv1, lo1);
        *(uint32_t*)(Oh + (size_t)gr0 * DM + col)       = h0;
        *(uint32_t*)(Ol + (size_t)gr0 * DM + col)       = lo0;
        *(uint32_t*)(Oh + (size_t)(gr0 + 8) * DM + col) = h1;
        *(uint32_t*)(Ol + (size_t)(gr0 + 8) * DM + col) = lo1;
    }
}

// ---------------------------------------------------------------------------
extern "C" void kernel_launch(void* const* d_in, const int* in_sizes, int n_in,
                              void* d_out, int out_size)
{
    const float* q    = (const float*)d_in[0];
    const float* k    = (const float*)d_in[1];
    const float* v    = (const float*)d_in[2];
    const int*   mask = (const int*)  d_in[3];
    const float* Wq   = (const float*)d_in[4];
    const float* bq   = (const float*)d_in[5];
    const float* Wk   = (const float*)d_in[6];
    const float* bk   = (const float*)d_in[7];
    const float* Wv   = (const float*)d_in[8];
    const float* bv   = (const float*)d_in[9];
    const float* Wo   = (const float*)d_in[10];
    const float* bo   = (const float*)d_in[11];
    float* out = (float*)d_out;

    __nv_bfloat16 *qh, *ql, *kh, *kl, *vh, *vl;
    __nv_bfloat16 *wqh, *wql, *wkh, *wkl, *wvh, *wvl, *woh, *wol;
    __nv_bfloat16 *Qph, *Qpl, *Kph, *Kpl, *Vph, *Vpl, *AOh, *AOl;
    cudaGetSymbolAddress((void**)&qh,  g_q_hi);  cudaGetSymbolAddress((void**)&ql,  g_q_lo);
    cudaGetSymbolAddress((void**)&kh,  g_k_hi);  cudaGetSymbolAddress((void**)&kl,  g_k_lo);
    cudaGetSymbolAddress((void**)&vh,  g_v_hi);  cudaGetSymbolAddress((void**)&vl,  g_v_lo);
    cudaGetSymbolAddress((void**)&wqh, g_Wq_hi); cudaGetSymbolAddress((void**)&wql, g_Wq_lo);
    cudaGetSymbolAddress((void**)&wkh, g_Wk_hi); cudaGetSymbolAddress((void**)&wkl, g_Wk_lo);
    cudaGetSymbolAddress((void**)&wvh, g_Wv_hi); cudaGetSymbolAddress((void**)&wvl, g_Wv_lo);
    cudaGetSymbolAddress((void**)&woh, g_Wo_hi); cudaGetSymbolAddress((void**)&wol, g_Wo_lo);
    cudaGetSymbolAddress((void**)&Qph, g_Qph);   cudaGetSymbolAddress((void**)&Qpl, g_Qpl);
    cudaGetSymbolAddress((void**)&Kph, g_Kph);   cudaGetSymbolAddress((void**)&Kpl, g_Kpl);
    cudaGetSymbolAddress((void**)&Vph, g_Vph);   cudaGetSymbolAddress((void**)&Vpl, g_Vpl);
    cudaGetSymbolAddress((void**)&AOh, g_AOh);   cudaGetSymbolAddress((void**)&AOl, g_AOl);

    cudaFuncSetAttribute(flash_attn_mma, cudaFuncAttributeMaxDynamicSharedMemorySize,
                         ATT_SMEM);

    const int n4_in = MROWS * DM / 4;
    const int n4_w  = DM * DM / 4;

    // mask all-ones check
    reset_flag<<<1, 1>>>();
    check_mask<<<1024, 256>>>(mask, S_LEN * S_LEN);

    // split inputs + weights to bf16 hi/lo
    split_bf16<<<n4_in / 256, 256>>>(q,  qh,  ql,  n4_in);
    split_bf16<<<n4_in / 256, 256>>>(k,  kh,  kl,  n4_in);
    split_bf16<<<n4_in / 256, 256>>>(v,  vh,  vl,  n4_in);
    split_bf16<<<n4_w  / 256, 256>>>(Wq, wqh, wql, n4_w);
    split_bf16<<<n4_w  / 256, 256>>>(Wk, wkh, wkl, n4_w);
    split_bf16<<<n4_w  / 256, 256>>>(Wv, wvh, wvl, n4_w);
    split_bf16<<<n4_w  / 256, 256>>>(Wo, woh, wol, n4_w);

    // fused Q/K/V projections -> bf16 hi/lo outputs
    GemmP pq = { qh, ql, wqh, wql, bq, nullptr, Qph, Qpl };
    GemmP pk = { kh, kl, wkh, wkl, bk, nullptr, Kph, Kpl };
    GemmP pv = { vh, vl, wvh, wvl, bv, nullptr, Vph, Vpl };
    dim3 gg3(DM / 128, MROWS / 128, 3);
    gemm_hmma<<<gg3, 256>>>(pq, pk, pv);

    // attention (HMMA) -> AO hi/lo
    dim3 ga(S_LEN / 128, B_SZ * NH);   // (16, 32)
    flash_attn_mma<<<ga, 256, ATT_SMEM>>>(Qph, Qpl, Kph, Kpl, Vph, Vpl, mask,
                                          AOh, AOl);

    // final projection -> fp32 out
    GemmP po = { AOh, AOl, woh, wol, bo, out, nullptr, nullptr };
    dim3 gg1(DM / 128, MROWS / 128, 1);
    gemm_hmma<<<gg1, 256>>>(po, po, po);
}